// round 16
// baseline (speedup 1.0000x reference)
#include <cuda_runtime.h>
#include <cuda_bf16.h>
#include <math.h>
#include <stdint.h>

#define MAX_E 320000
#define MAX_N 10000
#define NPAD  10112
#define HBITS 20
#define HSIZE (1 << HBITS)
#define HMASK (HSIZE - 1)

// ---------------- scratch ----------------
__device__ float g_efc[(size_t)MAX_E * 512];   // fallback path only
__device__ float g_h1 [(size_t)MAX_E * 384];   // relu(We1 out)
__device__ float g_qpe[(size_t)MAX_E * 256];   // tc: pe head-major [E*4][32]; fallback: q,pe halves
__device__ float g_v  [(size_t)MAX_E * 128];   // fallback path only
__device__ float g_efr [(size_t)MAX_E * 128];
__device__ float g_grev[(size_t)MAX_E * 128];
__device__ float g_xr[(size_t)NPAD * 128];
__device__ float g_xq[(size_t)NPAD * 128];     // head-major per node: [n][h*32+d]
__device__ float g_xv[(size_t)NPAD * 128];     // head-major per node: [n][h*32+d]
__device__ float g_xsd[(size_t)NPAD * 768];    // [xs | xd] node partials of We1
__device__ float g_zerob[768];
__device__ unsigned g_seg[MAX_N * 128];
__device__ float g_subj[MAX_N * 128];
__device__ float g_obj [MAX_N * 128];
__device__ int   g_cnt_s[MAX_N];
__device__ int   g_cnt_d[MAX_N];
__device__ int   g_hkey[HSIZE];
__device__ int   g_hval[HSIZE];
__device__ float g_twin_in[MAX_N * 256];
__device__ float g_twin  [MAX_N * 128];
__device__ float g_pin   [MAX_N * 256];
__device__ float g_hn    [MAX_N * 256];
__device__ float g_wt    [311552];

// tc-path layout inside g_wt
#define WT_WSD 0            // [768,128] K-contig: rows 0..383 = W_S, 384..767 = W_D
#define WT_WEG 98304        // [384,256] K-contig (We1 rows 128..383)
#define WT_WE2 196608
#define WT_WQ  245760
#define WT_WPE 262144
#define WT_WV  278528
#define WT_A1  294912
#define WT_A2  303104
#define WT_BA1 311296
#define WT_BA2 311424

// ---------------- helpers ----------------
__device__ __forceinline__ unsigned f2o(float f) {
    unsigned b = __float_as_uint(f);
    return (b & 0x80000000u) ? ~b : (b | 0x80000000u);
}
__device__ __forceinline__ float o2f(unsigned u) {
    return (u & 0x80000000u) ? __uint_as_float(u & 0x7fffffffu)
                             : __uint_as_float(~u);
}
__device__ __forceinline__ unsigned hash_of(unsigned k) {
    k *= 2654435761u;
    k ^= k >> 15;
    k *= 2246822519u;
    k ^= k >> 13;
    return k & HMASK;
}
__device__ __forceinline__ float tf32r(float x) {
    uint32_t u;
    asm("cvt.rna.tf32.f32 %0, %1;" : "=r"(u) : "f"(x));
    return __uint_as_float(u);
}
__device__ __forceinline__ uint32_t smem_u32(const void* p) {
    uint32_t a;
    asm("{ .reg .u64 t; cvta.to.shared.u64 t, %1; cvt.u32.u64 %0, t; }" : "=r"(a) : "l"(p));
    return a;
}
__device__ __forceinline__ uint32_t swz(uint32_t off) { return off ^ ((off >> 3) & 0x70); }

__device__ __forceinline__ void cp16(uint32_t dst, const void* src) {
    asm volatile("cp.async.cg.shared.global [%0], [%1], 16;" :: "r"(dst), "l"(src));
}
__device__ __forceinline__ void cp_commit() { asm volatile("cp.async.commit_group;"); }
__device__ __forceinline__ void cp_wait1()  { asm volatile("cp.async.wait_group 1;"); }
__device__ __forceinline__ void cp_wait0()  { asm volatile("cp.async.wait_group 0;"); }

__device__ __forceinline__ void ldm4(uint32_t* r, uint32_t addr) {
    asm volatile("ldmatrix.sync.aligned.m8n8.x4.shared.b16 {%0,%1,%2,%3}, [%4];"
        : "=r"(r[0]), "=r"(r[1]), "=r"(r[2]), "=r"(r[3]) : "r"(addr));
}
__device__ __forceinline__ void mma8(float* d, const uint32_t* a, uint32_t b0, uint32_t b1) {
    asm volatile(
        "mma.sync.aligned.m16n8k8.row.col.f32.tf32.tf32.f32 "
        "{%0,%1,%2,%3}, {%4,%5,%6,%7}, {%8,%9}, {%0,%1,%2,%3};"
        : "+f"(d[0]), "+f"(d[1]), "+f"(d[2]), "+f"(d[3])
        : "r"(a[0]), "r"(a[1]), "r"(a[2]), "r"(a[3]), "r"(b0), "r"(b1));
}

// ---------------- merged prep ----------------
__device__ __forceinline__ void trans_tile(const float* src, float* dst, int K, int N,
                                           int kb, int nb, int tx, int ty) {
    __shared__ float t[32][33];
    for (int i = ty; i < 32; i += 8) {
        int k = kb + i, n = nb + tx;
        t[i][tx] = (k < K && n < N) ? src[(size_t)k * N + n] : 0.f;
    }
    __syncthreads();
    for (int i = ty; i < 32; i += 8) {
        int n = nb + i, k = kb + tx;
        if (n < N && k < K) dst[(size_t)n * K + k] = tf32r(t[tx][i]);
    }
}

__global__ void prep_all(const float* We1, const float* We2, const float* Wq,
                         const float* Wpe, const float* Wv,
                         const float* A1, const float* a1,
                         const float* A2, const float* a2,
                         const float* x, int Nn, int npad) {
    int b = blockIdx.x;
    int tid = threadIdx.x;
    int tx = tid & 31, ty = tid >> 5;
    if (b < 512) {
        int stride = 512 * 256;
        int i0 = b * 256 + tid;
        for (int i = i0; i < HSIZE; i += stride) { g_hkey[i] = -1; g_hval[i] = 0x7fffffff; }
        int nc = Nn * 128;
        for (int i = i0; i < nc; i += stride) { g_seg[i] = 0u; g_subj[i] = 0.f; g_obj[i] = 0.f; }
        for (int i = i0; i < Nn; i += stride) { g_cnt_s[i] = 0; g_cnt_d[i] = 0; }
        for (int i = i0; i < 768; i += stride) g_zerob[i] = 0.f;
        return;
    }
    if (b >= 803) {
        int i = (b - 803) * 256 + tid;
        if (i < npad * 128)
            g_xr[i] = (i < Nn * 128) ? tf32r(x[i]) : 0.f;
        return;
    }
    b -= 512;
    if (b < 48) {            // W_S: We1 rows 0..127 -> WSD rows 0..383
        trans_tile(We1, g_wt + WT_WSD, 128, 384, (b / 12) * 32, (b % 12) * 32, tx, ty);
    } else if (b < 144) {    // W_EG: We1 rows 128..383 -> [384,256]
        int b2 = b - 48;
        trans_tile(We1 + 128 * 384, g_wt + WT_WEG, 256, 384, (b2 / 12) * 32, (b2 % 12) * 32, tx, ty);
    } else if (b < 192) {    // W_D: We1 rows 384..511 -> WSD rows 384..767
        int b2 = b - 144;
        trans_tile(We1 + 384 * 384, g_wt + WT_WSD + 384 * 128, 128, 384, (b2 / 12) * 32, (b2 % 12) * 32, tx, ty);
    } else if (b < 240) {
        b -= 192;
        trans_tile(We2, g_wt + WT_WE2, 384, 128, (b / 4) * 32, (b % 4) * 32, tx, ty);
    } else if (b < 256) {
        b -= 240;
        trans_tile(Wq, g_wt + WT_WQ, 128, 128, (b / 4) * 32, (b % 4) * 32, tx, ty);
    } else if (b < 272) {
        b -= 256;
        trans_tile(Wpe, g_wt + WT_WPE, 128, 128, (b / 4) * 32, (b % 4) * 32, tx, ty);
    } else if (b < 288) {
        b -= 272;
        trans_tile(Wv, g_wt + WT_WV, 128, 128, (b / 4) * 32, (b % 4) * 32, tx, ty);
    } else if (b == 288) {
        for (int i = tid; i < 8192; i += 256) {
            int n = i >> 6, k = i & 63;
            g_wt[WT_A1 + i] = (n < 64) ? tf32r(A1[n * 64 + k]) : 0.f;
        }
    } else if (b == 289) {
        for (int i = tid; i < 8192; i += 256) {
            int n = i >> 6, k = i & 63;
            g_wt[WT_A2 + i] = (n < 32) ? tf32r(A2[n * 64 + k]) : 0.f;
        }
    } else {
        if (tid < 128) g_wt[WT_BA1 + tid] = (tid < 64) ? a1[tid] : 0.f;
        else { int i = tid - 128; g_wt[WT_BA2 + i] = (i < 32) ? a2[i] : 0.f; }
    }
}

// ---------------- hash build ----------------
__global__ void hash_build(const int* __restrict__ ei, int E, int Nn) {
    int e = blockIdx.x * blockDim.x + threadIdx.x;
    if (e >= E) return;
    int s = ei[e], d = ei[E + e];
    unsigned key = (unsigned)s * (unsigned)Nn + (unsigned)d;
    unsigned h = hash_of(key);
    while (true) {
        int prev = atomicCAS(&g_hkey[h], -1, (int)key);
        if (prev == -1 || prev == (int)key) { atomicMin(&g_hval[h], e); break; }
        h = (h + 1) & HMASK;
    }
}

__device__ __forceinline__ int hash_find(unsigned key) {
    unsigned h = hash_of(key);
    while (true) {
        int k = g_hkey[h];
        if (k == (int)key) return g_hval[h];
        if (k == -1) return -1;
        h = (h + 1) & HMASK;
    }
}

// ---------------- persistent gather + gate + degrees (4 edges per warp) ----------------
__global__ __launch_bounds__(256)
void gather_gate(const float* __restrict__ ef, const int* __restrict__ ei,
                 const float* __restrict__ Wg1, const float* __restrict__ bg1,
                 const float* __restrict__ Wg2, const float* __restrict__ bg2,
                 int E, int Nn) {
    __shared__ __align__(16) float sW[128 * 64];
    __shared__ float sW2[64];
    __shared__ float sb1[64];
    __shared__ float sbg2;
    __shared__ __align__(16) float sefs[8][4][128];
    int t = threadIdx.x;
    for (int i = t; i < 128 * 64; i += 256) {
        int k = i >> 6, c = i & 63;
        int lane_i = c & 31, half = c >> 5;
        int kk = k >> 1, odd = k & 1;
        sW[(kk * 32 + lane_i) * 4 + odd * 2 + half] = Wg1[i];
    }
    if (t < 64) { sW2[t] = Wg2[t]; sb1[t] = bg1[t]; }
    if (t == 0) sbg2 = bg2[0];
    __syncthreads();
    int w = t >> 5, lane = t & 31;
    const float4* sW4 = (const float4*)sW;
    for (int e0 = blockIdx.x * 32 + w * 4; e0 < E; e0 += gridDim.x * 32) {
        int s[4], d[4];
        #pragma unroll
        for (int j = 0; j < 4; j++) { s[j] = ei[e0 + j]; d[j] = ei[E + e0 + j]; }
        float4 efv[4];
        #pragma unroll
        for (int j = 0; j < 4; j++) {
            efv[j] = ((const float4*)(ef + (size_t)(e0 + j) * 128))[lane];
            *(float4*)&sefs[w][j][lane * 4] = efv[j];
        }
        __syncwarp();
        float g0[4], g1[4];
        #pragma unroll
        for (int j = 0; j < 4; j++) { g0[j] = sb1[lane]; g1[j] = sb1[lane + 32]; }
        #pragma unroll 2
        for (int kk = 0; kk < 64; kk++) {
            float4 wp = sW4[kk * 32 + lane];
            #pragma unroll
            for (int j = 0; j < 4; j++) {
                float2 ev = *(const float2*)&sefs[w][j][kk * 2];
                g0[j] += ev.x * wp.x;
                g1[j] += ev.x * wp.y;
                g0[j] += ev.y * wp.z;
                g1[j] += ev.y * wp.w;
            }
        }
        float gate[4];
        #pragma unroll
        for (int j = 0; j < 4; j++) {
            float a = fmaxf(g0[j], 0.f), b = fmaxf(g1[j], 0.f);
            float p = a * sW2[lane] + b * sW2[lane + 32];
            #pragma unroll
            for (int off = 16; off; off >>= 1) p += __shfl_xor_sync(0xffffffffu, p, off);
            gate[j] = 1.f / (1.f + expf(-(p + sbg2)));
        }
        int rid = -1;
        if (lane < 4) {
            int j = lane;
            unsigned rkey = (unsigned)d[j] * (unsigned)Nn + (unsigned)s[j];
            rid = hash_find(rkey);
            atomicAdd(&g_cnt_s[s[j]], 1);
            atomicAdd(&g_cnt_d[d[j]], 1);
        }
        #pragma unroll
        for (int j = 0; j < 4; j++) {
            int rj = __shfl_sync(0xffffffffu, rid, j);
            float4 rv = make_float4(0.f, 0.f, 0.f, 0.f);
            if (rj >= 0) {
                rv = ((const float4*)(ef + (size_t)rj * 128))[lane];
                rv.x *= gate[j]; rv.y *= gate[j]; rv.z *= gate[j]; rv.w *= gate[j];
            }
            float4 efr;
            efr.x = tf32r(efv[j].x); efr.y = tf32r(efv[j].y);
            efr.z = tf32r(efv[j].z); efr.w = tf32r(efv[j].w);
            rv.x = tf32r(rv.x); rv.y = tf32r(rv.y); rv.z = tf32r(rv.z); rv.w = tf32r(rv.w);
            ((float4*)(g_efr  + (size_t)(e0 + j) * 128))[lane] = efr;
            ((float4*)(g_grev + (size_t)(e0 + j) * 128))[lane] = rv;
        }
        __syncwarp();
    }
}

// ---------------- tf32 mma.sync GEMM cores ----------------
#define GS 3
#define STAGE_BYTES 32768
#define G_SMEM (GS * STAGE_BYTES)

// 256-thread loader (64x32 engine)
__device__ __forceinline__ void g_load_chunk(const float* A, int lda, const float* Bt, int K,
                                             int m0, int n0, int c,
                                             uint32_t sa, int tid) {
    const float* ab = A + (size_t)m0 * lda + c * 32;
    const float* bb = Bt + (size_t)n0 * K + c * 32;
    uint32_t sb = sa + 16384u;
    #pragma unroll
    for (int i = 0; i < 4; i++) {
        int v = tid + (i << 8);
        int row = v >> 3, kq = v & 7;
        cp16(sa + swz(row * 128 + kq * 16), ab + (size_t)row * lda + kq * 4);
    }
    #pragma unroll
    for (int i = 0; i < 4; i++) {
        int v = tid + (i << 8);
        int row = v >> 3, kq = v & 7;
        cp16(sb + swz(row * 128 + kq * 16), bb + (size_t)row * K + kq * 4);
    }
}

// 128-thread loader (64x64 engine)
__device__ __forceinline__ void g_load_chunk128(const float* A, int lda, const float* Bt, int K,
                                                int m0, int n0, int c,
                                                uint32_t sa, int tid) {
    const float* ab = A + (size_t)m0 * lda + c * 32;
    const float* bb = Bt + (size_t)n0 * K + c * 32;
    uint32_t sb = sa + 16384u;
    #pragma unroll
    for (int i = 0; i < 8; i++) {
        int v = tid + (i << 7);
        int row = v >> 3, kq = v & 7;
        cp16(sa + swz(row * 128 + kq * 16), ab + (size_t)row * lda + kq * 4);
    }
    #pragma unroll
    for (int i = 0; i < 8; i++) {
        int v = tid + (i << 7);
        int row = v >> 3, kq = v & 7;
        cp16(sb + swz(row * 128 + kq * 16), bb + (size_t)row * K + kq * 4);
    }
}

#define GEMM_PIPE(LOADCALL, Kval, acc)                                                \
    const int a_row = wm + (lane & 15);                                               \
    const uint32_t a_chunk = ((lane >> 4) & 1) * 16;                                  \
    const uint32_t amask = (uint32_t)(a_row & 7) << 4;                                \
    uint32_t a_base[4];                                                               \
    _Pragma("unroll")                                                                 \
    for (int mt = 0; mt < 4; mt++) a_base[mt] = (uint32_t)(a_row + mt * 16) * 128u + a_chunk; \
    const int b_row = wn + ((lane >> 4) & 1) * 8 + (lane & 7);                        \
    const uint32_t b_chunk = ((lane >> 3) & 1) * 16;                                  \
    const uint32_t bmask = (uint32_t)(b_row & 7) << 4;                                \
    uint32_t b_base[2];                                                               \
    _Pragma("unroll")                                                                 \
    for (int g = 0; g < 2; g++) b_base[g] = (uint32_t)(b_row + g * 16) * 128u + b_chunk; \
    const int KC = (Kval) >> 5;                                                       \
    _Pragma("unroll")                                                                 \
    for (int c = 0; c < 2; c++) {                                                     \
        uint32_t sa = sbase + c * STAGE_BYTES;                                        \
        LOADCALL(c, sa);                                                              \
        cp_commit();                                                                  \
    }                                                                                 \
    for (int c = 0; c < KC; c++) {                                                    \
        cp_wait1();                                                                   \
        __syncthreads();                                                              \
        uint32_t sa = sbase + (c % GS) * STAGE_BYTES;                                 \
        uint32_t sb = sa + 16384u;                                                    \
        _Pragma("unroll")                                                             \
        for (int k8 = 0; k8 < 4; k8++) {                                              \
            uint32_t af[4][4], bf[2][4];                                              \
            _Pragma("unroll")                                                         \
            for (int mt = 0; mt < 4; mt++)                                            \
                ldm4(af[mt], sa + ((a_base[mt] + k8 * 32u) ^ amask));                 \
            _Pragma("unroll")                                                         \
            for (int g = 0; g < 2; g++)                                               \
                ldm4(bf[g], sb + ((b_base[g] + k8 * 32u) ^ bmask));                   \
            _Pragma("unroll")                                                         \
            for (int mt = 0; mt < 4; mt++)                                            \
                _Pragma("unroll")                                                     \
                for (int nt = 0; nt < 4; nt++)                                        \
                    mma8(acc[mt][nt], af[mt], bf[nt >> 1][(nt & 1) * 2],              \
                         bf[nt >> 1][(nt & 1) * 2 + 1]);                              \
        }                                                                             \
        int cn = c + 2;                                                               \
        if (cn < KC) {                                                                \
            uint32_t sn = sbase + (cn % GS) * STAGE_BYTES;                            \
            LOADCALL(cn, sn);                                                        \
        }                                                                             \
        cp_commit();                                                                  \
    }

// 128-thread 64x64 mainloop (acc[4][8][4])
#define GEMM_PIPE128(LOADCALL, Kval, acc)                                             \
    const int a_row = wm + (lane & 15);                                               \
    const uint32_t a_chunk = ((lane >> 4) & 1) * 16;                                  \
    const uint32_t amask = (uint32_t)(a_row & 7) << 4;                                \
    uint32_t a_base[4];                                                               \
    _Pragma("unroll")                                                                 \
    for (int mt = 0; mt < 4; mt++) a_base[mt] = (uint32_t)(a_row + mt * 16) * 128u + a_chunk; \
    const int b_row = wn + ((lane >> 4) & 1) * 8 + (lane & 7);                        \
    const uint32_t b_chunk = ((lane >> 3) & 1) * 16;                                  \
    const uint32_t bmask = (uint32_t)(b_row & 7) << 4;                                \
    uint32_t b_base[4];                                                               \
    _Pragma("unroll")                                                                 \
    for (int g = 0; g < 4; g++) b_base[g] = (uint32_t)(b_row + g * 16) * 128u + b_chunk; \
    const int KC = (Kval) >> 5;                                                       \
    _Pragma("unroll")                                                                 \
    for (int c = 0; c < 2; c++) {                                                     \
        uint32_t sa = sbase + c * STAGE_BYTES;                                        \
        LOADCALL(c, sa);                                                              \
        cp_commit();                                                                  \
    }                                                                                 \
    for (int c = 0; c < KC; c++) {                                                    \
        cp_wait1();                                                                   \
        __syncthreads();                                                              \
        uint32_t sa = sbase + (c % GS) * STAGE_BYTES;                                 \
        uint32_t sb = sa + 16384u;                                                    \
        _Pragma("unroll")                                                             \
        for (int k8 = 0; k8 < 4; k8++) {                                              \
            uint32_t af[4][4], bf[4][4];                                              \
            _Pragma("unroll")                                                         \
            for (int mt = 0; mt < 4; mt++)                                            \
                ldm4(af[mt], sa + ((a_base[mt] + k8 * 32u) ^ amask));                 \
            _Pragma("unroll")                                                         \
            for (int g = 0; g < 4; g++)                                               \
                ldm4(bf[g], sb + ((b_base[g] + k8 * 32u) ^ bmask));                   \
            _Pragma("unroll")                                                         \
            for (int mt = 0; mt < 4; mt++)                                            \
                _Pragma("unroll")                                                     \
                for (int nt = 0; nt < 8; nt++)                                        \
                    mma8(acc[mt][nt], af[mt], bf[nt >> 1][(nt & 1) * 2],              \
                         bf[nt >> 1][(nt & 1) * 2 + 1]);                              \
        }                                                                             \
        int cn = c + 2;                                                               \
        if (cn < KC) {                                                                \
            uint32_t sn = sbase + (cn % GS) * STAGE_BYTES;                            \
            LOADCALL(cn, sn);                                                        \
        }                                                                             \
        cp_commit();                                                                  \
    }

// ---------------- 256-thread generic GEMM ----------------
// mode bits: 1=relu, 2=tf32 round, 8=node head-major scalar
__global__ __launch_bounds__(256, 2)
void mma_gemm(const float* __restrict__ A, int lda,
              const float* __restrict__ Bt,
              const float* __restrict__ bias,
              float* __restrict__ C, int ldc,
              int K, int mode, int Ncols, int coff, int qldc) {
    extern __shared__ char dyn_smem[];
    __shared__ float s_bias[128];
    const uint32_t sbase = smem_u32(dyn_smem);
    const int tid = threadIdx.x;
    const int wid = tid >> 5;
    const int lane = tid & 31;
    const int m0 = blockIdx.y * 128;
    const int n0 = blockIdx.x * 128;
    const int wm = (wid & 1) * 64;
    const int wn = (wid >> 1) * 32;

    if (tid < 128) s_bias[tid] = bias[n0 + tid];

    float acc[4][4][4];
    #pragma unroll
    for (int i = 0; i < 4; i++)
        #pragma unroll
        for (int j = 0; j < 4; j++)
            #pragma unroll
            for (int q = 0; q < 4; q++) acc[i][j][q] = 0.f;

    #define LC_STD(c, sa) g_load_chunk(A, lda, Bt, K, m0, n0, c, sa, tid)
    GEMM_PIPE(LC_STD, K, acc)
    #undef LC_STD

    const int rbase = m0 + wm + (lane >> 2);
    const int cl = (lane & 3) * 2;
    #pragma unroll
    for (int mt = 0; mt < 4; mt++) {
        #pragma unroll
        for (int nt = 0; nt < 4; nt++) {
            int ncol_l = wn + nt * 8 + cl;
            if (ncol_l >= Ncols) continue;
            float b0 = s_bias[ncol_l], b1 = s_bias[ncol_l + 1];
            int ncol = n0 + ncol_l;
            #pragma unroll
            for (int half = 0; half < 2; half++) {
                int row = rbase + mt * 16 + half * 8;
                float v0 = acc[mt][nt][half * 2 + 0] + b0;
                float v1 = acc[mt][nt][half * 2 + 1] + b1;
                if (mode & 1) { v0 = fmaxf(v0, 0.f); v1 = fmaxf(v1, 0.f); }
                if (mode & 2) { v0 = tf32r(v0); v1 = tf32r(v1); }
                if (mode & 8) {
                    C[(size_t)row * 128 + (ncol & 3) * 32 + (ncol >> 2)] = v0;
                    int nc1 = ncol + 1;
                    C[(size_t)row * 128 + (nc1 & 3) * 32 + (nc1 >> 2)] = v1;
                } else {
                    *(float2*)(C + (size_t)row * ldc + ncol) = make_float2(v0, v1);
                }
            }
        }
    }
}

// ---------------- 128-thread generic GEMM (pe projection; staged permute) ----------------
__global__ __launch_bounds__(128, 2)
void mma_gemm128(const float* __restrict__ A, int lda,
                 const float* __restrict__ Bt,
                 const float* __restrict__ bias,
                 float* __restrict__ C,
                 int K, int mode) {
    extern __shared__ char dyn_smem[];
    __shared__ float s_bias[128];
    const uint32_t sbase = smem_u32(dyn_smem);
    const int tid = threadIdx.x;
    const int wid = tid >> 5;
    const int lane = tid & 31;
    const int m0 = blockIdx.y * 128;
    const int n0 = 0;
    const int wm = (wid & 1) * 64;
    const int wn = (wid >> 1) * 64;

    s_bias[tid] = bias[tid];

    float acc[4][8][4];
    #pragma unroll
    for (int i = 0; i < 4; i++)
        #pragma unroll
        for (int j = 0; j < 8; j++)
            #pragma unroll
            for (int q = 0; q < 4; q++) acc[i][j][q] = 0.f;

    #define LC_STD128(c, sa) g_load_chunk128(A, lda, Bt, K, m0, n0, c, sa, tid)
    GEMM_PIPE128(LC_STD128, K, acc)
    #undef LC_STD128

    cp_wait0();
    __syncthreads();
    float* sC = (float*)dyn_smem;   // 16384 floats
    const int rl_base = wm + (lane >> 2);
    const int cl = (lane & 3) * 2;
    #pragma unroll
    for (int mt = 0; mt < 4; mt++) {
        #pragma unroll
        for (int nt = 0; nt < 8; nt++) {
            int ncol = wn + nt * 8 + cl;
            float b0 = s_bias[ncol], b1 = s_bias[ncol + 1];
            #pragma unroll
            for (int half = 0; half < 2; half++) {
                int rl = rl_base + mt * 16 + half * 8;
                float v0 = acc[mt][nt][half * 2 + 0] + b0;
                float v1 = acc[mt][nt][half * 2 + 1] + b1;
                if (mode & 1) { v0 = fmaxf(v0, 0.f); v1 = fmaxf(v1, 0.f); }
                if (mode & 2) { v0 = tf32r(v0); v1 = tf32r(v1); }
                sC[(rl * 4 + (ncol & 3)) * 32 + (ncol >> 2)] = v0;
                int nc1 = ncol + 1;
                sC[(rl * 4 + (nc1 & 3)) * 32 + (nc1 >> 2)] = v1;
            }
        }
    }
    __syncthreads();
    float4* outp = (float4*)(C + (size_t)m0 * 128);
    const float4* sC4 = (const float4*)sC;
    #pragma unroll
    for (int i = 0; i < 32; i++) outp[tid + i * 128] = sC4[tid + i * 128];
}

// ---------------- We1 edge GEMM (K=256 over efr|grev) + node-partial epilogue ----------------
__global__ __launch_bounds__(128, 2)
void mma_gemm_we1(const float* __restrict__ Bt,
                  const float* __restrict__ bias,
                  float* __restrict__ C, int ldc,
                  const int* __restrict__ ei, int E) {
    extern __shared__ char dyn_smem[];
    __shared__ float s_bias[128];
    __shared__ int s_src[128], s_dst[128];
    const uint32_t sbase = smem_u32(dyn_smem);
    const int tid = threadIdx.x;
    const int wid = tid >> 5;
    const int lane = tid & 31;
    const int m0 = blockIdx.y * 128;
    const int n0 = blockIdx.x * 128;
    const int wm = (wid & 1) * 64;
    const int wn = (wid >> 1) * 64;

    s_bias[tid] = bias[n0 + tid];
    s_src[tid] = ei[m0 + tid];
    s_dst[tid] = ei[E + m0 + tid];
    __syncthreads();

    float acc[4][8][4];
    #pragma unroll
    for (int i = 0; i < 4; i++)
        #pragma unroll
        for (int j = 0; j < 8; j++)
            #pragma unroll
            for (int q = 0; q < 4; q++) acc[i][j][q] = 0.f;

#define WE1_LOAD(c, sa_) do {                                                         \
    int seg = (c) >> 2, cbase = ((c) & 3) * 32;                                       \
    uint32_t sb_ = (sa_) + 16384u;                                                    \
    _Pragma("unroll")                                                                 \
    for (int i = 0; i < 8; i++) {                                                     \
        int v = tid + (i << 7);                                                       \
        int row = v >> 3, kq = v & 7;                                                 \
        int col = cbase + kq * 4;                                                     \
        const float* srcp = (seg == 0 ? g_efr : g_grev) + (size_t)(m0 + row) * 128 + col; \
        cp16((sa_) + swz(row * 128 + kq * 16), srcp);                                 \
    }                                                                                 \
    const float* bb = Bt + (size_t)n0 * 256 + (c) * 32;                               \
    _Pragma("unroll")                                                                 \
    for (int i = 0; i < 8; i++) {                                                     \
        int v = tid + (i << 7);                                                       \
        int row = v >> 3, kq = v & 7;                                                 \
        cp16(sb_ + swz(row * 128 + kq * 16), bb + (size_t)row * 256 + kq * 4);        \
    }                                                                                 \
} while (0)

    GEMM_PIPE128(WE1_LOAD, 256, acc)
#undef WE1_LOAD

    const int rl0 = wm + (lane >> 2);
    const int cl = (lane & 3) * 2;
    #pragma unroll
    for (int mt = 0; mt < 4; mt++) {
        #pragma unroll
        for (int nt = 0; nt < 8; nt++) {
            int ncol_l = wn + nt * 8 + cl;
            float b0 = s_bias[ncol_l], b1 = s_bias[ncol_l + 1];
            int ncol = n0 + ncol_l;
            #pragma unroll
            for (int half = 0; half < 2; half++) {
                int rl = rl0 + mt * 16 + half * 8;
                int row = m0 + rl;
                float2 xsv = *(const float2*)(g_xsd + (size_t)s_src[rl] * 768 + ncol);
                float2 xdv = *(const float2*)(g_xsd + (size_t)s_dst[rl] * 768 + 384 + ncol);
                float v0 = tf32r(fmaxf(acc[mt][nt][half * 2 + 0] + b0 + xsv.x + xdv.x, 0.f));
                float v1 = tf32r(fmaxf(acc[mt][nt][half * 2 + 1] + b1 + xsv.y + xdv.y, 0.f));
                *(float2*)(C + (size_t)row * ldc + ncol) = make_float2(v0, v1);
            }
        }
    }
}

// ---------------- We2 GEMM (128-thread 64x64) with fused LayerNorm + scatter ----------------
__global__ __launch_bounds__(128, 2)
void mma_gemm_ln128(const float* __restrict__ A, int lda,
                    const float* __restrict__ Bt,
                    const float* __restrict__ bias,
                    float* __restrict__ C,
                    int K,
                    const float* __restrict__ ge, const float* __restrict__ be,
                    const int* __restrict__ ei, int E) {
    extern __shared__ char dyn_smem[];
    __shared__ float s_bias[128];
    __shared__ float s_ge[128];
    __shared__ float s_be[128];
    const uint32_t sbase = smem_u32(dyn_smem);
    const int tid = threadIdx.x;
    const int wid = tid >> 5;
    const int lane = tid & 31;
    const int m0 = blockIdx.y * 128;
    const int n0 = 0;
    const int wm = (wid & 1) * 64;
    const int wn = (wid >> 1) * 64;

    s_bias[tid] = bias[tid];
    s_ge[tid] = ge[tid];
    s_be[tid] = be[tid];

    float acc[4][8][4];
    #pragma unroll
    for (int i = 0; i < 4; i++)
        #pragma unroll
        for (int j = 0; j < 8; j++)
            #pragma unroll
            for (int q = 0; q < 4; q++) acc[i][j][q] = 0.f;

    #define LC_STD128(c, sa) g_load_chunk128(A, lda, Bt, K, m0, n0, c, sa, tid)
    GEMM_PIPE128(LC_STD128, K, acc)
    #undef LC_STD128

    cp_wait0();
    __syncthreads();
    float* sC = (float*)dyn_smem;   // [128][132]
    const int rl_base = wm + (lane >> 2);
    const int cl = (lane & 3) * 2;
    #pragma unroll
    for (int mt = 0; mt < 4; mt++) {
        #pragma unroll
        for (int nt = 0; nt < 8; nt++) {
            int ncol = wn + nt * 8 + cl;
            float b0 = s_bias[ncol], b1 = s_bias[ncol + 1];
            #pragma unroll
            for (int half = 0; half < 2; half++) {
                int rl = rl_base + mt * 16 + half * 8;
                sC[rl * 132 + ncol]     = acc[mt][nt][half * 2 + 0] + b0;
                sC[rl * 132 + ncol + 1] = acc[mt][nt][half * 2 + 1] + b1;
            }
        }
    }
    __syncthreads();
    for (int r = wid; r < 128; r += 4) {
        float4 v = ((float4*)(sC + r * 132))[lane];
        float s = v.x + v.y + v.z + v.w;
        float sq = v.x * v.x + v.y * v.y + v.z * v.z + v.w * v.w;
        #pragma unroll
        for (int off = 16; off; off >>= 1) {
            s  += __shfl_xor_sync(0xffffffffu, s,  off);
            sq += __shfl_xor_sync(0xffffffffu, sq, off);
        }
        float m = s * (1.f / 128.f);
        float var = sq * (1.f / 128.f) - m * m;
        float inv = rsqrtf(var + 1e-5f);
        int e = m0 + r;
        int si = ei[e], di = ei[E + e];
        float* pv = &v.x;
        #pragma unroll
        for (int j = 0; j < 4; j++) {
            int c = lane * 4 + j;
            float val = (pv[j] - m) * inv * s_ge[c] + s_be[c];
            pv[j] = val;
            atomicAdd(&g_subj[si * 128 + c], val);
            atomicAdd(&g_obj[di * 128 + c], val);
        }
        ((float4*)(C + (size_t)e * 128))[lane] = v;
    }
}

// ---------------- fused attention MLP + softmax + scatter-max ----------------
#define AT_SMEM ((4352 + 2176 + 8704 + 8704 + 64 + 32) * 4)
__global__ __launch_bounds__(256, 2)
void attn_fused(const float* __restrict__ pe, const int* __restrict__ ei, int E) {
    extern __shared__ float sm[];
    float* sA1 = sm;
    float* sA2 = sA1 + 4352;
    float* sq  = sA2 + 2176;
    float* st1 = sq + 8704;
    float* sb1 = st1 + 8704;
    float* sb2 = sb1 + 64;
    const int tid = threadIdx.x, wid = tid >> 5, lane = tid & 31;
    for (int i = tid; i < 64 * 64; i += 256) sA1[(i >> 6) * 68 + (i & 63)] = g_wt[WT_A1 + i];
    for (int i = tid; i < 32 * 64; i += 256) sA2[(i >> 6) * 68 + (i & 63)] = g_wt[WT_A2 + i];
    if (tid < 64) sb1[tid] = g_wt[WT_BA1 + tid];
    else if (tid < 96) sb2[tid - 64] = g_wt[WT_BA2 + tid - 64];

    const int R0 = blockIdx.x * 128 + wid * 16;
    float* mysq = sq + wid * 1088;
    float* myt1 = st1 + wid * 1088;
    const float* gpe = pe + (size_t)R0 * 32;
    #pragma unroll
    for (int i = 0; i < 4; i++) {
        int v = lane + i * 32;
        int r = v >> 3, c4 = v & 7;
        float4 pv = ((const float4*)(gpe + r * 32))[c4];
        *(float4*)(mysq + r * 68 + 32 + c4 * 4) = pv;
    }
    #pragma unroll
    for (int r = 0; r < 16; r++) {
        int gr = R0 + r;
        int e = gr >> 2, h = gr & 3;
        int s = ei[e];
        mysq[r * 68 + lane] = g_xq[(size_t)s * 128 + h * 32 + lane];
    }
    __syncthreads();

    const int qr = lane >> 2, qk = lane & 3;
    float acc1[8][4];
    #pragma unroll
    for (int nt = 0; nt < 8; nt++)
        #pragma unroll
        for (int q = 0; q < 4; q++) acc1[nt][q] = 0.f;
    #pragma unroll
    for (int kc = 0; kc < 8; kc++) {
        uint32_t a[4];
        a[0] = __float_as_uint(mysq[qr * 68 + kc * 8 + qk]);
        a[1] = __float_as_uint(mysq[(qr + 8) * 68 + kc * 8 + qk]);
        a[2] = __float_as_uint(mysq[qr * 68 + kc * 8 + qk + 4]);
        a[3] = __float_as_uint(mysq[(qr + 8) * 68 + kc * 8 + qk + 4]);
        #pragma unroll
        for (int nt = 0; nt < 8; nt++) {
            uint32_t b0 = __float_as_uint(sA1[(nt * 8 + qr) * 68 + kc * 8 + qk]);
            uint32_t b1 = __float_as_uint(sA1[(nt * 8 + qr) * 68 + kc * 8 + qk + 4]);
            mma8(acc1[nt], a, b0, b1);
        }
    }
    #pragma unroll
    for (int nt = 0; nt < 8; nt++) {
        int c0 = nt * 8 + 2 * qk;
        float b0v = sb1[c0], b1v = sb1[c0 + 1];
        myt1[qr * 68 + c0]           = tf32r(fmaxf(acc1[nt][0] + b0v, 0.f));
        myt1[qr * 68 + c0 + 1]       = tf32r(fmaxf(acc1[nt][1] + b1v, 0.f));
        myt1[(qr + 8) * 68 + c0]     = tf32r(fmaxf(acc1[nt][2] + b0v, 0.f));
        myt1[(qr + 8) * 68 + c0 + 1] = tf32r(fmaxf(acc1[nt][3] + b1v, 0.f));
    }
    __syncwarp();
    float acc2[4][4];
    #pragma unroll
    for (int nt = 0; nt < 4; nt++)
        #pragma unroll
        for (int q = 0; q < 4; q++) acc2[nt][q] = 0.f;
    #pragma unroll
    for (int kc = 0; kc < 8; kc++) {
        uint32_t a[4];
        a[0] = __float_as_uint(myt1[qr * 68 + kc * 8 + qk]);
        a[1] = __float_as_uint(myt1[(qr + 8) * 68 + kc * 8 + qk]);
        a[2] = __float_as_uint(myt1[qr * 68 + kc * 8 + qk + 4]);
        a[3] = __float_as_uint(myt1[(qr + 8) * 68 + kc * 8 + qk + 4]);
        #pragma unroll
        for (int nt = 0; nt < 4; nt++) {
            uint32_t b0 = __float_as_uint(sA2[(nt * 8 + qr) * 68 + kc * 8 + qk]);
            uint32_t b1 = __float_as_uint(sA2[(nt * 8 + qr) * 68 + kc * 8 + qk + 4]);
            mma8(acc2[nt], a, b0, b1);
        }
    }
    float vlo[8], vhi[8];
    #pragma unroll
    for (int nt = 0; nt < 4; nt++) {
        int c0 = nt * 8 + 2 * qk;
        vlo[nt * 2]     = acc2[nt][0] + sb2[c0];
        vlo[nt * 2 + 1] = acc2[nt][1] + sb2[c0 + 1];
        vhi[nt * 2]     = acc2[nt][2] + sb2[c0];
        vhi[nt * 2 + 1] = acc2[nt][3] + sb2[c0 + 1];
    }
    float mlo = vlo[0], mhi = vhi[0];
    #pragma unroll
    for (int i = 1; i < 8; i++) { mlo = fmaxf(mlo, vlo[i]); mhi = fmaxf(mhi, vhi[i]); }
    mlo = fmaxf(mlo, __shfl_xor_sync(0xffffffffu, mlo, 1));
    mlo = fmaxf(mlo, __shfl_xor_sync(0xffffffffu, mlo, 2));
    mhi = fmaxf(mhi, __shfl_xor_sync(0xffffffffu, mhi, 1));
    mhi = fmaxf(mhi, __shfl_xor_sync(0xffffffffu, mhi, 2));
    float slo = 0.f, shi = 0.f;
    #pragma unroll
    for (int i = 0; i < 8; i++) {
        vlo[i] = expf(vlo[i] - mlo); slo += vlo[i];
        vhi[i] = expf(vhi[i] - mhi); shi += vhi[i];
    }
    slo += __shfl_xor_sync(0xffffffffu, slo, 1);
    slo += __shfl_xor_sync(0xffffffffu, slo, 2);
    shi += __shfl_xor_sync(0xffffffffu, shi, 1);
    shi += __shfl_xor_sync(0xffffffffu, shi, 2);
    float rlo = 1.f / slo, rhi = 1.f / shi;
    int Rlo = R0 + qr, Rhi = R0 + qr + 8;
    int elo = Rlo >> 2, hlo = Rlo & 3;
    int ehi = Rhi >> 2, hhi = Rhi & 3;
    int silo = ei[elo], sihi = ei[ehi];
    int dlo = ei[E + elo], dhi = ei[E + ehi];
    const float* vblo = g_xv + (size_t)dlo * 128 + hlo * 32;
    const float* vbhi = g_xv + (size_t)dhi * 128 + hhi * 32;
    unsigned* seglo = g_seg + silo * 128 + hlo;
    unsigned* seghi = g_seg + sihi * 128 + hhi;
    #pragma unroll
    for (int nt = 0; nt < 4; nt++) {
        #pragma unroll
        for (int j = 0; j < 2; j++) {
            int o = nt * 8 + 2 * qk + j;
            float xlo = vlo[nt * 2 + j] * rlo * vblo[o];
            atomicMax(&seglo[o * 4], f2o(xlo));
            float xhi = vhi[nt * 2 + j] * rhi * vbhi[o];
            atomicMax(&seghi[o * 4], f2o(xhi));
        }
    }
}

// ---------------- generic tiled fp32 SGEMM (node GEMMs + fallback) ----------------
__global__ __launch_bounds__(128)
void sgemm(const float* __restrict__ A, int lda,
           const float* __restrict__ W,
           const float* __restrict__ bias,
           float* __restrict__ C, int ldc,
           int M, int K, int N, int act) {
    __shared__ __align__(16) float As[16][64];
    __shared__ __align__(16) float Bs[16][64];
    int t = threadIdx.x;
    int m0 = blockIdx.y * 64;
    int n0 = blockIdx.x * 64;
    int tx = t & 15;
    int ty = t >> 4;
    float acc[8][4];
    #pragma unroll
    for (int i = 0; i < 8; i++)
        #pragma unroll
        for (int j = 0; j < 4; j++) acc[i][j] = 0.f;

    for (int k0 = 0; k0 < K; k0 += 16) {
        #pragma unroll
        for (int i = 0; i < 2; i++) {
            int v = t * 2 + i;
            int row = v >> 2;
            int kq = v & 3;
            float4 av = make_float4(0.f, 0.f, 0.f, 0.f);
            int gr = m0 + row;
            if (gr < M) av = *(const float4*)(A + (size_t)gr * lda + k0 + kq * 4);
            As[kq * 4 + 0][row] = av.x;
            As[kq * 4 + 1][row] = av.y;
            As[kq * 4 + 2][row] = av.z;
            As[kq * 4 + 3][row] = av.w;
        }
        #pragma unroll
        for (int i = 0; i < 2; i++) {
            int v = t * 2 + i;
            int kr = v >> 4;
            int nq = v & 15;
            *(float4*)&Bs[kr][nq * 4] = *(const float4*)(W + (size_t)(k0 + kr) * N + n0 + nq * 4);
        }
        __syncthreads();
        #pragma unroll
        for (int kk = 0; kk < 16; kk++) {
            float a[8], b[4];
            *(float4*)&a[0] = *(float4*)&As[kk][ty * 8];
            *(float4*)&a[4] = *(float4*)&As[kk][ty * 8 + 4];
            *(float4*)&b[0] = *(float4*)&Bs[kk][tx * 4];
            #pragma unroll
            for (int i = 0; i < 8; i++)
                #pragma unroll
                for (int j = 0; j < 4; j++) acc[i][j] += a[i] * b[j];
        }
        __syncthreads();
    }
    float bv[4];
    #pragma unroll
    for (int j = 0; j < 4; j++) bv[j] = bias[n0 + tx * 4 + j];
    #pragma unroll
    for (int i = 0; i < 8; i++) {
        int gr = m0 + ty * 8 + i;
        if (gr >= M) continue;
        float4 o;
        float* po = &o.x;
        #pragma unroll
        for (int j = 0; j < 4; j++) {
            float v = acc[i][j] + bv[j];
            if (act) v = fmaxf(v, 0.f);
            po[j] = v;
        }
        *(float4*)(C + (size_t)gr * ldc + n0 + tx * 4) = o;
    }
}

// ================= legacy fallback kernels (E % 128 != 0 only) =================
__global__ void gather_gate_legacy(const float* __restrict__ x, const float* __restrict__ ef,
                                   const int* __restrict__ ei,
                                   const float* __restrict__ Wg1, const float* __restrict__ bg1,
                                   const float* __restrict__ Wg2, const float* __restrict__ bg2,
                                   int E, int Nn) {
    __shared__ __align__(16) float sW[128 * 64];
    __shared__ float sW2[64];
    __shared__ float sb1[64];
    __shared__ float sbg2;
    __shared__ __align__(16) float sefs[8][128];
    int t = threadIdx.x;
    for (int i = t; i < 128 * 64; i += 256) sW[i] = Wg1[i];
    if (t < 64) { sW2[t] = Wg2[t]; sb1[t] = bg1[t]; }
    if (t == 0) sbg2 = bg2[0];
    __syncthreads();
    int w = t >> 5, lane = t & 31;
    int e = blockIdx.x * 8 + w;
    if (e >= E) return;
    int s = ei[e], d = ei[E + e];
    float4 efv = ((const float4*)(ef + (size_t)e * 128))[lane];
    *(float4*)&sefs[w][lane * 4] = efv;
    __syncwarp();
    float g0 = sb1[lane], g1 = sb1[lane + 32];
    #pragma unroll 8
    for (int k = 0; k < 128; k++) {
        float ev = sefs[w][k];
        g0 += ev * sW[k * 64 + lane];
        g1 += ev * sW[k * 64 + lane + 32];
    }
    g0 = fmaxf(g0, 0.f); g1 = fmaxf(g1, 0.f);
    float p = g0 * sW2[lane] + g1 * sW2[lane + 32];
    #pragma unroll
    for (int off = 16; off; off >>= 1) p += __shfl_xor_sync(0xffffffffu, p, off);
    float gate = 1.f / (1.f + expf(-(p + sbg2)));
    int rid = -1;
    if (lane == 0) {
        unsigned rkey = (unsigned)d * (unsigned)Nn + (unsigned)s;
        rid = hash_find(rkey);
        atomicAdd(&g_cnt_s[s], 1);
        atomicAdd(&g_cnt_d[d], 1);
    }
    rid = __shfl_sync(0xffffffffu, rid, 0);
    float4 rv = make_float4(0.f, 0.f, 0.f, 0.f);
    if (rid >= 0) {
        rv = ((const float4*)(ef + (size_t)rid * 128))[lane];
        rv.x *= gate; rv.y *= gate; rv.z *= gate; rv.w *= gate;
    }
    float4 xi = ((const float4*)(x + (size_t)s * 128))[lane];
    float4 xj = ((const float4*)(x + (size_t)d * 128))[lane];
    float* dst = g_efc + (size_t)e * 512;
    ((float4*)dst)[lane]          = xi;
    ((float4*)(dst + 128))[lane]  = efv;
    ((float4*)(dst + 256))[lane]  = rv;
    ((float4*)(dst + 384))[lane]  = xj;
}

__global__ void edge_ln_scatter(float* __restrict__ out_edge,
                                const float* __restrict__ ge, const float* __restrict__ be,
                                const int* __restrict__ ei, int E) {
    int t = threadIdx.x;
    int w = t >> 5, lane = t & 31;
    int e = blockIdx.x * 8 + w;
    if (e >= E) return;
    float* row = out_edge + (size_t)e * 128;
    float4 v = ((float4*)row)[lane];
    float s = v.x + v.y + v.z + v.w;
    float sq = v.x * v.x + v.y * v.y + v.z * v.z + v.w * v.w;
    #pragma unroll
    for (int off = 16; off; off >>= 1) {
        s  += __shfl_xor_sync(0xffffffffu, s,  off);
        sq += __shfl_xor_sync(0xffffffffu, sq, off);
    }
    float m = s * (1.f / 128.f);
    float var = sq * (1.f / 128.f) - m * m;
    float inv = rsqrtf(var + 1e-5f);
    int si = ei[e], di = ei[E + e];
    float* pv = &v.x;
    #pragma unroll
    for (int j = 0; j < 4; j++) {
        int c = lane * 4 + j;
        float val = (pv[j] - m) * inv * ge[c] + be[c];
        pv[j] = val;
        atomicAdd(&g_subj[si * 128 + c], val);
        atomicAdd(&g_obj[di * 128 + c], val);
    }
    ((float4*)row)[lane] = v;
}

__global__ __launch_bounds__(128)
void attention_kernel(const float* __restrict__ qb, const float* __restrict__ peb,
                      const float* __restrict__ vb,
                      const float* __restrict__ A1, const float* __restrict__ a1,
                      const float* __restrict__ A2, const float* __restrict__ a2,
                      const int* __restrict__ ei, int E) {
    __shared__ float sA1[64 * 64];
    __shared__ float sA2[32 * 64];
    __shared__ float sa1[64], sa2[32];
    int t = threadIdx.x;
    for (int i = t; i < 4096; i += 128) sA1[i] = A1[i];
    for (int i = t; i < 2048; i += 128) sA2[i] = A2[i];
    if (t < 64) sa1[t] = a1[t];
    if (t < 32) sa2[t] = a2[t];
    __syncthreads();
    int p = blockIdx.x * 128 + t;
    if (p >= E * 4) return;
    int e = p >> 2, h = p & 3;
    const float* qr = qb + (size_t)e * 128 + h;
    const float* pr = peb + (size_t)e * 128 + h;
    float hv[64];
    #pragma unroll
    for (int c = 0; c < 32; c++) { hv[c] = qr[c * 4]; hv[32 + c] = pr[c * 4]; }
    float t1[64];
    #pragma unroll
    for (int o = 0; o < 64; o++) {
        float acc = sa1[o];
        #pragma unroll
        for (int c = 0; c < 64; c++) acc += sA1[o * 64 + c] * hv[c];
        t1[o] = fmaxf(acc, 0.f);
    }
    float t2[32];
    float mx = -1e30f;
    #pragma unroll
    for (int o = 0; o < 32; o++) {
        float acc = sa2[o];
        #pragma unroll
        for (int c = 0; c < 64; c++) acc += sA2[o * 64 + c] * t1[c];
        t2[o] = acc;
        mx = fmaxf(mx, acc);
    }
    float ssum = 0.f;
    #pragma unroll
    for (int o = 0; o < 32; o++) { t2[o] = expf(t2[o] - mx); ssum += t2[o]; }
    float rs = 1.f / ssum;
    int s = ei[e];
    const float* vr = vb + (size_t)e * 128 + h;
    unsigned* segb = g_seg + s * 128 + h;
    #pragma unroll
    for (int o = 0; o < 32; o++) {
        float xxv = t2[o] * rs * vr[o * 4];
        atomicMax(&segb[o * 4], f2o(xxv));
    }
}

// ---------------- node pipeline ----------------
__global__ void node_pre1(int Nn) {
    int i = blockIdx.x * 256 + threadIdx.x;
    if (i >= Nn * 128) return;
    int n = i >> 7, c = i & 127;
    float cs = fmaxf((float)g_cnt_s[n], 1.f);
    float cd = fmaxf((float)g_cnt_d[n], 1.f);
    g_twin_in[n * 256 + c]       = g_subj[i] / cs;
    g_twin_in[n * 256 + 128 + c] = g_obj[i] / cd;
}

__global__ void node_pre2(const float* __restrict__ x, int Nn) {
    int i = blockIdx.x * 256 + threadIdx.x;
    if (i >= Nn * 128) return;
    int n = i >> 7, c = i & 127;
    float tw = g_twin[i];
    float sg = 1.f / (1.f + expf(-tw));
    float xx = 0.f;
    if (g_cnt_s[n] > 0) xx = fmaxf(o2f(g_seg[i]), 0.f);
    g_pin[n * 256 + c]       = x[i];
    g_pin[n * 256 + 128 + c] = xx * sg;
}

__global__ void node_ln(float* __restrict__ out_node,
                        const float* __restrict__ gn, const float* __restrict__ bn,
                        int Nn) {
    int t = threadIdx.x;
    int w = t >> 5, lane = t & 31;
    int n = blockIdx.x * 8 + w;
    if (n >= Nn) return;
    float* row = out_node + (size_t)n * 128;
    float4 v = ((float4*)row)[lane];
    float s = v.x + v.y + v.z + v.w;
    float sq = v.x * v.x + v.y * v.y + v.z * v.z + v.w * v.w;
    #pragma unroll
    for (int off = 16; off; off >>= 1) {
        s  += __shfl_xor_sync(0xffffffffu, s,  off);
        sq += __shfl_xor_sync(0xffffffffu, sq, off);
    }
    float m = s * (1.f / 128.f);
    float var = sq * (1.f / 128.f) - m * m;
    float inv = rsqrtf(var + 1e-5f);
    float* pv = &v.x;
    #pragma unroll
    for (int j = 0; j < 4; j++) {
        int c = lane * 4 + j;
        pv[j] = (pv[j] - m) * inv * gn[c] + bn[c];
    }
    ((float4*)row)[lane] = v;
}

// ---------------- launch ----------------
extern "C" void kernel_launch(void* const* d_in, const int* in_sizes, int n_in,
                              void* d_out, int out_size) {
    const float* x    = (const float*)d_in[0];
    const float* ef   = (const float*)d_in[1];
    const int*   ei   = (const int*)  d_in[2];
    const float* Wg1  = (const float*)d_in[3];
    const float* bg1  = (const float*)d_in[4];
    const float* Wg2  = (const float*)d_in[5];
    const float* bg2  = (const float*)d_in[6];
    const float* We1  = (const float*)d_in[7];
    const float* be1  = (const float*)d_in[8];
    const float* We2  = (const float*)d_in[9];
    const float* be2  = (const float*)d_in[10];
    const float* ge   = (const float*)d_in[11];
    const float* bee  = (const float*)d_in[12];
    const float* Wq   = (const float*)d_in[13];
    const float* bq   = (const float*)d_in[14];
    const float* Wpe  = (const float*)d_in[15];
    const float* bpe  = (const float*)d_in[16];
    const float* Wv   = (const float*)d_in[17];
    const float* bv   = (const float*)d_in[18];
    const float* A1   = (const float*)d_in[19];
    const float* a1   = (const float*)d_in[20];
    const float* A2   = (const float*)d_in[21];
    const float* a2   = (const float*)d_in[22];
    const float* Wt   = (const float*)d_in[23];
    const float* bt   = (const float*)d_in[24];
    const float* Wp1  = (const float*)d_in[25];
    const float* bp1  = (const float*)d_in[26];
    const float* Wp2  = (const float*)d_in[27];
    const float* bp2  = (const float*)d_in[28];
    const float* gn   = (const float*)d_in[29];
    const float* bn   = (const float*)d_in[30];

    int Nn = in_sizes[0] / 128;
    int E  = in_sizes[1] / 128;

    float* out_node = (float*)d_out;
    float* out_edge = out_node + (size_t)Nn * 128;

    float *p_efc, *p_h1, *p_qpe, *p_v, *p_efr, *p_xr, *p_xq, *p_xv, *p_xsd, *p_zb;
    float *p_twin_in, *p_twin, *p_pin, *p_hn, *p_wt;
    cudaGetSymbolAddress((void**)&p_efc, g_efc);
    cudaGetSymbolAddress((void**)&p_h1,  g_h1);
    cudaGetSymbolAddress((void**)&p_qpe, g_qpe);
    cudaGetSymbolAddress((void**)&p_v,   g_v);
    cudaGetSymbolAddress((void**)&p_efr, g_efr);
    cudaGetSymbolAddress((void**)&p_xr,  g_xr);
    cudaGetSymbolAddress((void**)&p_xq,  g_xq);
    cudaGetSymbolAddress((void**)&p_xv,  g_xv);
    cudaGetSymbolAddress((void**)&p_xsd, g_xsd);
    cudaGetSymbolAddress((void**)&p_zb,  g_zerob);
    cudaGetSymbolAddress((void**)&p_twin_in, g_twin_in);
    cudaGetSymbolAddress((void**)&p_twin, g_twin);
    cudaGetSymbolAddress((void**)&p_pin, g_pin);
    cudaGetSymbolAddress((void**)&p_hn,  g_hn);
    cudaGetSymbolAddress((void**)&p_wt,  g_wt);

    cudaFuncSetAttribute(mma_gemm, cudaFuncAttributeMaxDynamicSharedMemorySize, G_SMEM);
    cudaFuncSetAttribute(mma_gemm128, cudaFuncAttributeMaxDynamicSharedMemorySize, G_SMEM);
    cudaFuncSetAttribute(mma_gemm_we1, cudaFuncAttributeMaxDynamicSharedMemorySize, G_SMEM);
    cudaFuncSetAttribute(mma_gemm_ln128, cudaFuncAttributeMaxDynamicSharedMemorySize, G_SMEM);
    cudaFuncSetAttribute(attn_fused, cudaFuncAttributeMaxDynamicSharedMemorySize, AT_SMEM);

    int gNn = (Nn + 63) / 64;
    int ntiles = (Nn + 127) / 128;
    int npad = ntiles * 128;
    bool use_tc = (E % 128) == 0 && Nn <= MAX_N;
    int rx_blocks = (npad * 128 + 255) / 256;
    int prep_blocks = 512 + 291 + rx_blocks;

    if (use_tc) {
        int mt = E / 128;
        int gg_blocks = (E + 31) / 32;
        if (gg_blocks > 1184) gg_blocks = 1184;
        prep_all<<<prep_blocks, 256>>>(We1, We2, Wq, Wpe, Wv, A1, a1, A2, a2, x, Nn, npad);
        // node partials of We1: xsd = [xr@W_S^T | xr@W_D^T]
        mma_gemm<<<dim3(6, ntiles), 256, G_SMEM>>>(p_xr, 128, p_wt + WT_WSD, p_zb, p_xsd, 768, 128, 0, 128, 0, 0);
        hash_build<<<(E + 255) / 256, 256>>>(ei, E, Nn);
        gather_gate<<<gg_blocks, 256>>>(ef, ei, Wg1, bg1, Wg2, bg2, E, Nn);
        mma_gemm_we1<<<dim3(3, mt), 128, G_SMEM>>>(p_wt + WT_WEG, be1, p_h1, 384, ei, E);
        mma_gemm<<<dim3(1, ntiles), 256, G_SMEM>>>(p_xr, 128, p_wt + WT_WQ, bq, p_xq, 0, 128, 10, 128, 0, 0);
        mma_gemm<<<dim3(1, ntiles), 256, G_SMEM>>>(p_xr, 128, p_wt + WT_WV, bv, p_xv, 0, 128, 8, 128, 0, 0);
        mma_gemm_ln128<<<dim3(1, mt), 128, G_SMEM>>>(p_h1, 384, p_wt + WT_WE2, be2, out_edge, 384, ge, bee, ei, E);
        mma_gemm128<<<dim3(1, mt), 128, G_SMEM>>>(p_efr, 128, p_wt + WT_WPE, bpe, p_qpe, 128, 2);
        attn_fused<<<E / 32, 256, AT_SMEM>>>(p_qpe, ei, E);
    } else {
        prep_all<<<prep_blocks, 256>>>(We1, We2, Wq, Wpe, Wv, A1, a1, A2, a2, x, Nn, npad);
        hash_build<<<(E + 255) / 256, 256>>>(ei, E, Nn);
        int gE = (E + 63) / 64;
        float* p_q  = p_qpe;
        float* p_pe = p_qpe + (size_t)E * 128;
        gather_gate_legacy<<<(E + 7) / 8, 256>>>(x, ef, ei, Wg1, bg1, Wg2, bg2, E, Nn);
        sgemm<<<dim3(6, gE), 128>>>(p_efc, 512, We1, be1, p_h1, 384, E, 512, 384, 1);
        sgemm<<<dim3(2, gE), 128>>>(p_h1, 384, We2, be2, out_edge, 128, E, 384, 128, 0);
        edge_ln_scatter<<<(E + 7) / 8, 256>>>(out_edge, ge, bee, ei, E);
        sgemm<<<dim3(2, gE), 128>>>(p_efc +   0, 512, Wq,  bq,  p_q,  128, E, 128, 128, 0);
        sgemm<<<dim3(2, gE), 128>>>(p_efc + 128, 512, Wpe, bpe, p_pe, 128, E, 128, 128, 0);
        sgemm<<<dim3(2, gE), 128>>>(p_efc + 384, 512, Wv,  bv,  p_v,  128, E, 128, 128, 0);
        attention_kernel<<<(E * 4 + 127) / 128, 128>>>(p_q, p_pe, p_v, A1, a1, A2, a2, ei, E);
    }

    node_pre1<<<(Nn * 128 + 255) / 256, 256>>>(Nn);
    sgemm<<<dim3(2, gNn), 128>>>(p_twin_in, 256, Wt, bt, p_twin, 128, Nn, 256, 128, 0);
    node_pre2<<<(Nn * 128 + 255) / 256, 256>>>(x, Nn);
    sgemm<<<dim3(4, gNn), 128>>>(p_pin, 256, Wp1, bp1, p_hn, 256, Nn, 256, 256, 1);
    sgemm<<<dim3(2, gNn), 128>>>(p_hn, 256, Wp2, bp2, out_node, 128, Nn, 256, 128, 0);
    node_ln<<<(Nn + 7) / 8, 256>>>(out_node, gn, bn, Nn);
}

// round 17
// speedup vs baseline: 1.0905x; 1.0905x over previous
#include <cuda_runtime.h>
#include <cuda_bf16.h>
#include <math.h>
#include <stdint.h>

#define MAX_E 320000
#define MAX_N 10000
#define NPAD  10112
#define HBITS 20
#define HSIZE (1 << HBITS)
#define HMASK (HSIZE - 1)

// ---------------- scratch ----------------
__device__ float g_efc[(size_t)MAX_E * 512];   // fallback path only
__device__ float g_h1 [(size_t)MAX_E * 384];   // relu(We1 out)
__device__ float g_qpe[(size_t)MAX_E * 256];   // tc: pe head-major [E*4][32]; fallback: q,pe halves
__device__ float g_v  [(size_t)MAX_E * 128];   // fallback path only
__device__ float g_efr [(size_t)MAX_E * 128];
__device__ float g_grev[(size_t)MAX_E * 128];
__device__ float g_xr[(size_t)NPAD * 128];
__device__ float g_xq[(size_t)NPAD * 128];     // head-major per node: [n][h*32+d]
__device__ float g_xv[(size_t)NPAD * 128];     // head-major per node: [n][h*32+d]
__device__ unsigned g_seg[MAX_N * 128];
__device__ float g_subj[MAX_N * 128];
__device__ float g_obj [MAX_N * 128];
__device__ int   g_cnt_s[MAX_N];
__device__ int   g_cnt_d[MAX_N];
__device__ int   g_hkey[HSIZE];
__device__ int   g_hval[HSIZE];
__device__ float g_twin_in[MAX_N * 256];
__device__ float g_twin  [MAX_N * 128];
__device__ float g_pin   [MAX_N * 256];
__device__ float g_hn    [MAX_N * 256];
__device__ float g_wt    [311552];

#define WT_WE1 0
#define WT_WE2 196608
#define WT_WQ  245760
#define WT_WPE 262144
#define WT_WV  278528
#define WT_A1  294912
#define WT_A2  303104
#define WT_BA1 311296
#define WT_BA2 311424

// ---------------- helpers ----------------
__device__ __forceinline__ unsigned f2o(float f) {
    unsigned b = __float_as_uint(f);
    return (b & 0x80000000u) ? ~b : (b | 0x80000000u);
}
__device__ __forceinline__ float o2f(unsigned u) {
    return (u & 0x80000000u) ? __uint_as_float(u & 0x7fffffffu)
                             : __uint_as_float(~u);
}
__device__ __forceinline__ unsigned hash_of(unsigned k) {
    k *= 2654435761u;
    k ^= k >> 15;
    k *= 2246822519u;
    k ^= k >> 13;
    return k & HMASK;
}
__device__ __forceinline__ float tf32r(float x) {
    uint32_t u;
    asm("cvt.rna.tf32.f32 %0, %1;" : "=r"(u) : "f"(x));
    return __uint_as_float(u);
}
__device__ __forceinline__ uint32_t smem_u32(const void* p) {
    uint32_t a;
    asm("{ .reg .u64 t; cvta.to.shared.u64 t, %1; cvt.u32.u64 %0, t; }" : "=r"(a) : "l"(p));
    return a;
}
__device__ __forceinline__ uint32_t swz(uint32_t off) { return off ^ ((off >> 3) & 0x70); }

__device__ __forceinline__ void cp16(uint32_t dst, const void* src) {
    asm volatile("cp.async.cg.shared.global [%0], [%1], 16;" :: "r"(dst), "l"(src));
}
__device__ __forceinline__ void cp_commit() { asm volatile("cp.async.commit_group;"); }
__device__ __forceinline__ void cp_wait1()  { asm volatile("cp.async.wait_group 1;"); }
__device__ __forceinline__ void cp_wait0()  { asm volatile("cp.async.wait_group 0;"); }

__device__ __forceinline__ void ldm4(uint32_t* r, uint32_t addr) {
    asm volatile("ldmatrix.sync.aligned.m8n8.x4.shared.b16 {%0,%1,%2,%3}, [%4];"
        : "=r"(r[0]), "=r"(r[1]), "=r"(r[2]), "=r"(r[3]) : "r"(addr));
}
__device__ __forceinline__ void mma8(float* d, const uint32_t* a, uint32_t b0, uint32_t b1) {
    asm volatile(
        "mma.sync.aligned.m16n8k8.row.col.f32.tf32.tf32.f32 "
        "{%0,%1,%2,%3}, {%4,%5,%6,%7}, {%8,%9}, {%0,%1,%2,%3};"
        : "+f"(d[0]), "+f"(d[1]), "+f"(d[2]), "+f"(d[3])
        : "r"(a[0]), "r"(a[1]), "r"(a[2]), "r"(a[3]), "r"(b0), "r"(b1));
}

// ---------------- merged prep ----------------
__device__ __forceinline__ void trans_tile(const float* src, float* dst, int K, int N,
                                           int kb, int nb, int tx, int ty) {
    __shared__ float t[32][33];
    for (int i = ty; i < 32; i += 8) {
        int k = kb + i, n = nb + tx;
        t[i][tx] = (k < K && n < N) ? src[(size_t)k * N + n] : 0.f;
    }
    __syncthreads();
    for (int i = ty; i < 32; i += 8) {
        int n = nb + i, k = kb + tx;
        if (n < N && k < K) dst[(size_t)n * K + k] = tf32r(t[tx][i]);
    }
}

__global__ void prep_all(const float* We1, const float* We2, const float* Wq,
                         const float* Wpe, const float* Wv,
                         const float* A1, const float* a1,
                         const float* A2, const float* a2,
                         const float* x, int Nn, int npad) {
    int b = blockIdx.x;
    int tid = threadIdx.x;
    int tx = tid & 31, ty = tid >> 5;
    if (b < 512) {
        int stride = 512 * 256;
        int i0 = b * 256 + tid;
        for (int i = i0; i < HSIZE; i += stride) { g_hkey[i] = -1; g_hval[i] = 0x7fffffff; }
        int nc = Nn * 128;
        for (int i = i0; i < nc; i += stride) { g_seg[i] = 0u; g_subj[i] = 0.f; g_obj[i] = 0.f; }
        for (int i = i0; i < Nn; i += stride) { g_cnt_s[i] = 0; g_cnt_d[i] = 0; }
        return;
    }
    if (b >= 803) {
        int i = (b - 803) * 256 + tid;
        if (i < npad * 128)
            g_xr[i] = (i < Nn * 128) ? tf32r(x[i]) : 0.f;
        return;
    }
    b -= 512;
    if (b < 192) {
        trans_tile(We1, g_wt + WT_WE1, 512, 384, (b / 12) * 32, (b % 12) * 32, tx, ty);
    } else if (b < 240) {
        b -= 192;
        trans_tile(We2, g_wt + WT_WE2, 384, 128, (b / 4) * 32, (b % 4) * 32, tx, ty);
    } else if (b < 256) {
        b -= 240;
        trans_tile(Wq, g_wt + WT_WQ, 128, 128, (b / 4) * 32, (b % 4) * 32, tx, ty);
    } else if (b < 272) {
        b -= 256;
        trans_tile(Wpe, g_wt + WT_WPE, 128, 128, (b / 4) * 32, (b % 4) * 32, tx, ty);
    } else if (b < 288) {
        b -= 272;
        trans_tile(Wv, g_wt + WT_WV, 128, 128, (b / 4) * 32, (b % 4) * 32, tx, ty);
    } else if (b == 288) {
        for (int i = tid; i < 8192; i += 256) {
            int n = i >> 6, k = i & 63;
            g_wt[WT_A1 + i] = (n < 64) ? tf32r(A1[n * 64 + k]) : 0.f;
        }
    } else if (b == 289) {
        for (int i = tid; i < 8192; i += 256) {
            int n = i >> 6, k = i & 63;
            g_wt[WT_A2 + i] = (n < 32) ? tf32r(A2[n * 64 + k]) : 0.f;
        }
    } else {
        if (tid < 128) g_wt[WT_BA1 + tid] = (tid < 64) ? a1[tid] : 0.f;
        else { int i = tid - 128; g_wt[WT_BA2 + i] = (i < 32) ? a2[i] : 0.f; }
    }
}

// ---------------- hash build ----------------
__global__ void hash_build(const int* __restrict__ ei, int E, int Nn) {
    int e = blockIdx.x * blockDim.x + threadIdx.x;
    if (e >= E) return;
    int s = ei[e], d = ei[E + e];
    unsigned key = (unsigned)s * (unsigned)Nn + (unsigned)d;
    unsigned h = hash_of(key);
    while (true) {
        int prev = atomicCAS(&g_hkey[h], -1, (int)key);
        if (prev == -1 || prev == (int)key) { atomicMin(&g_hval[h], e); break; }
        h = (h + 1) & HMASK;
    }
}

__device__ __forceinline__ int hash_find(unsigned key) {
    unsigned h = hash_of(key);
    while (true) {
        int k = g_hkey[h];
        if (k == (int)key) return g_hval[h];
        if (k == -1) return -1;
        h = (h + 1) & HMASK;
    }
}

// ---------------- persistent gather + gate + degrees (4 edges per warp) ----------------
__global__ __launch_bounds__(256)
void gather_gate(const float* __restrict__ ef, const int* __restrict__ ei,
                 const float* __restrict__ Wg1, const float* __restrict__ bg1,
                 const float* __restrict__ Wg2, const float* __restrict__ bg2,
                 int E, int Nn) {
    __shared__ __align__(16) float sW[128 * 64];
    __shared__ float sW2[64];
    __shared__ float sb1[64];
    __shared__ float sbg2;
    __shared__ __align__(16) float sefs[8][4][128];
    int t = threadIdx.x;
    for (int i = t; i < 128 * 64; i += 256) {
        int k = i >> 6, c = i & 63;
        int lane_i = c & 31, half = c >> 5;
        int kk = k >> 1, odd = k & 1;
        sW[(kk * 32 + lane_i) * 4 + odd * 2 + half] = Wg1[i];
    }
    if (t < 64) { sW2[t] = Wg2[t]; sb1[t] = bg1[t]; }
    if (t == 0) sbg2 = bg2[0];
    __syncthreads();
    int w = t >> 5, lane = t & 31;
    const float4* sW4 = (const float4*)sW;
    for (int e0 = blockIdx.x * 32 + w * 4; e0 < E; e0 += gridDim.x * 32) {
        int s[4], d[4];
        #pragma unroll
        for (int j = 0; j < 4; j++) { s[j] = ei[e0 + j]; d[j] = ei[E + e0 + j]; }
        float4 efv[4];
        #pragma unroll
        for (int j = 0; j < 4; j++) {
            efv[j] = ((const float4*)(ef + (size_t)(e0 + j) * 128))[lane];
            *(float4*)&sefs[w][j][lane * 4] = efv[j];
        }
        __syncwarp();
        float g0[4], g1[4];
        #pragma unroll
        for (int j = 0; j < 4; j++) { g0[j] = sb1[lane]; g1[j] = sb1[lane + 32]; }
        #pragma unroll 2
        for (int kk = 0; kk < 64; kk++) {
            float4 wp = sW4[kk * 32 + lane];
            #pragma unroll
            for (int j = 0; j < 4; j++) {
                float2 ev = *(const float2*)&sefs[w][j][kk * 2];
                g0[j] += ev.x * wp.x;
                g1[j] += ev.x * wp.y;
                g0[j] += ev.y * wp.z;
                g1[j] += ev.y * wp.w;
            }
        }
        float gate[4];
        #pragma unroll
        for (int j = 0; j < 4; j++) {
            float a = fmaxf(g0[j], 0.f), b = fmaxf(g1[j], 0.f);
            float p = a * sW2[lane] + b * sW2[lane + 32];
            #pragma unroll
            for (int off = 16; off; off >>= 1) p += __shfl_xor_sync(0xffffffffu, p, off);
            gate[j] = 1.f / (1.f + expf(-(p + sbg2)));
        }
        int rid = -1;
        if (lane < 4) {
            int j = lane;
            unsigned rkey = (unsigned)d[j] * (unsigned)Nn + (unsigned)s[j];
            rid = hash_find(rkey);
            atomicAdd(&g_cnt_s[s[j]], 1);
            atomicAdd(&g_cnt_d[d[j]], 1);
        }
        #pragma unroll
        for (int j = 0; j < 4; j++) {
            int rj = __shfl_sync(0xffffffffu, rid, j);
            float4 rv = make_float4(0.f, 0.f, 0.f, 0.f);
            if (rj >= 0) {
                rv = ((const float4*)(ef + (size_t)rj * 128))[lane];
                rv.x *= gate[j]; rv.y *= gate[j]; rv.z *= gate[j]; rv.w *= gate[j];
            }
            float4 efr;
            efr.x = tf32r(efv[j].x); efr.y = tf32r(efv[j].y);
            efr.z = tf32r(efv[j].z); efr.w = tf32r(efv[j].w);
            rv.x = tf32r(rv.x); rv.y = tf32r(rv.y); rv.z = tf32r(rv.z); rv.w = tf32r(rv.w);
            ((float4*)(g_efr  + (size_t)(e0 + j) * 128))[lane] = efr;
            ((float4*)(g_grev + (size_t)(e0 + j) * 128))[lane] = rv;
        }
        __syncwarp();
    }
}

// ---------------- tf32 mma.sync GEMM cores ----------------
#define GS 3
#define STAGE_BYTES 32768
#define G_SMEM (GS * STAGE_BYTES)

// 256-thread loader (64x32 engine)
__device__ __forceinline__ void g_load_chunk(const float* A, int lda, const float* Bt, int K,
                                             int m0, int n0, int c,
                                             uint32_t sa, int tid) {
    const float* ab = A + (size_t)m0 * lda + c * 32;
    const float* bb = Bt + (size_t)n0 * K + c * 32;
    uint32_t sb = sa + 16384u;
    #pragma unroll
    for (int i = 0; i < 4; i++) {
        int v = tid + (i << 8);
        int row = v >> 3, kq = v & 7;
        cp16(sa + swz(row * 128 + kq * 16), ab + (size_t)row * lda + kq * 4);
    }
    #pragma unroll
    for (int i = 0; i < 4; i++) {
        int v = tid + (i << 8);
        int row = v >> 3, kq = v & 7;
        cp16(sb + swz(row * 128 + kq * 16), bb + (size_t)row * K + kq * 4);
    }
}

// 128-thread loader (64x64 engine)
__device__ __forceinline__ void g_load_chunk128(const float* A, int lda, const float* Bt, int K,
                                                int m0, int n0, int c,
                                                uint32_t sa, int tid) {
    const float* ab = A + (size_t)m0 * lda + c * 32;
    const float* bb = Bt + (size_t)n0 * K + c * 32;
    uint32_t sb = sa + 16384u;
    #pragma unroll
    for (int i = 0; i < 8; i++) {
        int v = tid + (i << 7);
        int row = v >> 3, kq = v & 7;
        cp16(sa + swz(row * 128 + kq * 16), ab + (size_t)row * lda + kq * 4);
    }
    #pragma unroll
    for (int i = 0; i < 8; i++) {
        int v = tid + (i << 7);
        int row = v >> 3, kq = v & 7;
        cp16(sb + swz(row * 128 + kq * 16), bb + (size_t)row * K + kq * 4);
    }
}

#define GEMM_PIPE(LOADCALL, Kval, acc)                                                \
    const int a_row = wm + (lane & 15);                                               \
    const uint32_t a_chunk = ((lane >> 4) & 1) * 16;                                  \
    const uint32_t amask = (uint32_t)(a_row & 7) << 4;                                \
    uint32_t a_base[4];                                                               \
    _Pragma("unroll")                                                                 \
    for (int mt = 0; mt < 4; mt++) a_base[mt] = (uint32_t)(a_row + mt * 16) * 128u + a_chunk; \
    const int b_row = wn + ((lane >> 4) & 1) * 8 + (lane & 7);                        \
    const uint32_t b_chunk = ((lane >> 3) & 1) * 16;                                  \
    const uint32_t bmask = (uint32_t)(b_row & 7) << 4;                                \
    uint32_t b_base[2];                                                               \
    _Pragma("unroll")                                                                 \
    for (int g = 0; g < 2; g++) b_base[g] = (uint32_t)(b_row + g * 16) * 128u + b_chunk; \
    const int KC = (Kval) >> 5;                                                       \
    _Pragma("unroll")                                                                 \
    for (int c = 0; c < 2; c++) {                                                     \
        uint32_t sa = sbase + c * STAGE_BYTES;                                        \
        LOADCALL(c, sa);                                                              \
        cp_commit();                                                                  \
    }                                                                                 \
    for (int c = 0; c < KC; c++) {                                                    \
        cp_wait1();                                                                   \
        __syncthreads();                                                              \
        uint32_t sa = sbase + (c % GS) * STAGE_BYTES;                                 \
        uint32_t sb = sa + 16384u;                                                    \
        _Pragma("unroll")                                                             \
        for (int k8 = 0; k8 < 4; k8++) {                                              \
            uint32_t af[4][4], bf[2][4];                                              \
            _Pragma("unroll")                                                         \
            for (int mt = 0; mt < 4; mt++)                                            \
                ldm4(af[mt], sa + ((a_base[mt] + k8 * 32u) ^ amask));                 \
            _Pragma("unroll")                                                         \
            for (int g = 0; g < 2; g++)                                               \
                ldm4(bf[g], sb + ((b_base[g] + k8 * 32u) ^ bmask));                   \
            _Pragma("unroll")                                                         \
            for (int mt = 0; mt < 4; mt++)                                            \
                _Pragma("unroll")                                                     \
                for (int nt = 0; nt < 4; nt++)                                        \
                    mma8(acc[mt][nt], af[mt], bf[nt >> 1][(nt & 1) * 2],              \
                         bf[nt >> 1][(nt & 1) * 2 + 1]);                              \
        }                                                                             \
        int cn = c + 2;                                                               \
        if (cn < KC) {                                                                \
            uint32_t sn = sbase + (cn % GS) * STAGE_BYTES;                            \
            LOADCALL(cn, sn);                                                        \
        }                                                                             \
        cp_commit();                                                                  \
    }

// 128-thread 64x64 mainloop (acc[4][8][4])
#define GEMM_PIPE128(LOADCALL, Kval, acc)                                             \
    const int a_row = wm + (lane & 15);                                               \
    const uint32_t a_chunk = ((lane >> 4) & 1) * 16;                                  \
    const uint32_t amask = (uint32_t)(a_row & 7) << 4;                                \
    uint32_t a_base[4];                                                               \
    _Pragma("unroll")                                                                 \
    for (int mt = 0; mt < 4; mt++) a_base[mt] = (uint32_t)(a_row + mt * 16) * 128u + a_chunk; \
    const int b_row = wn + ((lane >> 4) & 1) * 8 + (lane & 7);                        \
    const uint32_t b_chunk = ((lane >> 3) & 1) * 16;                                  \
    const uint32_t bmask = (uint32_t)(b_row & 7) << 4;                                \
    uint32_t b_base[4];                                                               \
    _Pragma("unroll")                                                                 \
    for (int g = 0; g < 4; g++) b_base[g] = (uint32_t)(b_row + g * 16) * 128u + b_chunk; \
    const int KC = (Kval) >> 5;                                                       \
    _Pragma("unroll")                                                                 \
    for (int c = 0; c < 2; c++) {                                                     \
        uint32_t sa = sbase + c * STAGE_BYTES;                                        \
        LOADCALL(c, sa);                                                              \
        cp_commit();                                                                  \
    }                                                                                 \
    for (int c = 0; c < KC; c++) {                                                    \
        cp_wait1();                                                                   \
        __syncthreads();                                                              \
        uint32_t sa = sbase + (c % GS) * STAGE_BYTES;                                 \
        uint32_t sb = sa + 16384u;                                                    \
        _Pragma("unroll")                                                             \
        for (int k8 = 0; k8 < 4; k8++) {                                              \
            uint32_t af[4][4], bf[4][4];                                              \
            _Pragma("unroll")                                                         \
            for (int mt = 0; mt < 4; mt++)                                            \
                ldm4(af[mt], sa + ((a_base[mt] + k8 * 32u) ^ amask));                 \
            _Pragma("unroll")                                                         \
            for (int g = 0; g < 4; g++)                                               \
                ldm4(bf[g], sb + ((b_base[g] + k8 * 32u) ^ bmask));                   \
            _Pragma("unroll")                                                         \
            for (int mt = 0; mt < 4; mt++)                                            \
                _Pragma("unroll")                                                     \
                for (int nt = 0; nt < 8; nt++)                                        \
                    mma8(acc[mt][nt], af[mt], bf[nt >> 1][(nt & 1) * 2],              \
                         bf[nt >> 1][(nt & 1) * 2 + 1]);                              \
        }                                                                             \
        int cn = c + 2;                                                               \
        if (cn < KC) {                                                                \
            uint32_t sn = sbase + (cn % GS) * STAGE_BYTES;                            \
            LOADCALL(cn, sn);                                                        \
        }                                                                             \
        cp_commit();                                                                  \
    }

// ---------------- 256-thread generic GEMM (xq/xv node projections) ----------------
// mode bits: 1=relu, 2=tf32 round, 8=node head-major scalar
__global__ __launch_bounds__(256, 2)
void mma_gemm(const float* __restrict__ A, int lda,
              const float* __restrict__ Bt,
              const float* __restrict__ bias,
              float* __restrict__ C, int ldc,
              int K, int mode, int Ncols, int coff, int qldc) {
    extern __shared__ char dyn_smem[];
    __shared__ float s_bias[128];
    const uint32_t sbase = smem_u32(dyn_smem);
    const int tid = threadIdx.x;
    const int wid = tid >> 5;
    const int lane = tid & 31;
    const int m0 = blockIdx.y * 128;
    const int n0 = blockIdx.x * 128;
    const int wm = (wid & 1) * 64;
    const int wn = (wid >> 1) * 32;

    if (tid < 128) s_bias[tid] = bias[n0 + tid];

    float acc[4][4][4];
    #pragma unroll
    for (int i = 0; i < 4; i++)
        #pragma unroll
        for (int j = 0; j < 4; j++)
            #pragma unroll
            for (int q = 0; q < 4; q++) acc[i][j][q] = 0.f;

    #define LC_STD(c, sa) g_load_chunk(A, lda, Bt, K, m0, n0, c, sa, tid)
    GEMM_PIPE(LC_STD, K, acc)
    #undef LC_STD

    const int rbase = m0 + wm + (lane >> 2);
    const int cl = (lane & 3) * 2;
    #pragma unroll
    for (int mt = 0; mt < 4; mt++) {
        #pragma unroll
        for (int nt = 0; nt < 4; nt++) {
            int ncol_l = wn + nt * 8 + cl;
            if (ncol_l >= Ncols) continue;
            float b0 = s_bias[ncol_l], b1 = s_bias[ncol_l + 1];
            int ncol = n0 + ncol_l;
            #pragma unroll
            for (int half = 0; half < 2; half++) {
                int row = rbase + mt * 16 + half * 8;
                float v0 = acc[mt][nt][half * 2 + 0] + b0;
                float v1 = acc[mt][nt][half * 2 + 1] + b1;
                if (mode & 1) { v0 = fmaxf(v0, 0.f); v1 = fmaxf(v1, 0.f); }
                if (mode & 2) { v0 = tf32r(v0); v1 = tf32r(v1); }
                if (mode & 8) {
                    C[(size_t)row * 128 + (ncol & 3) * 32 + (ncol >> 2)] = v0;
                    int nc1 = ncol + 1;
                    C[(size_t)row * 128 + (nc1 & 3) * 32 + (nc1 >> 2)] = v1;
                } else {
                    *(float2*)(C + (size_t)row * ldc + ncol) = make_float2(v0, v1);
                }
            }
        }
    }
}

// ---------------- 128-thread generic GEMM (pe projection; staged permute) ----------------
__global__ __launch_bounds__(128, 2)
void mma_gemm128(const float* __restrict__ A, int lda,
                 const float* __restrict__ Bt,
                 const float* __restrict__ bias,
                 float* __restrict__ C,
                 int K, int mode) {
    extern __shared__ char dyn_smem[];
    __shared__ float s_bias[128];
    const uint32_t sbase = smem_u32(dyn_smem);
    const int tid = threadIdx.x;
    const int wid = tid >> 5;
    const int lane = tid & 31;
    const int m0 = blockIdx.y * 128;
    const int n0 = 0;
    const int wm = (wid & 1) * 64;
    const int wn = (wid >> 1) * 64;

    s_bias[tid] = bias[tid];

    float acc[4][8][4];
    #pragma unroll
    for (int i = 0; i < 4; i++)
        #pragma unroll
        for (int j = 0; j < 8; j++)
            #pragma unroll
            for (int q = 0; q < 4; q++) acc[i][j][q] = 0.f;

    #define LC_STD128(c, sa) g_load_chunk128(A, lda, Bt, K, m0, n0, c, sa, tid)
    GEMM_PIPE128(LC_STD128, K, acc)
    #undef LC_STD128

    cp_wait0();
    __syncthreads();
    float* sC = (float*)dyn_smem;   // 16384 floats
    const int rl_base = wm + (lane >> 2);
    const int cl = (lane & 3) * 2;
    #pragma unroll
    for (int mt = 0; mt < 4; mt++) {
        #pragma unroll
        for (int nt = 0; nt < 8; nt++) {
            int ncol = wn + nt * 8 + cl;
            float b0 = s_bias[ncol], b1 = s_bias[ncol + 1];
            #pragma unroll
            for (int half = 0; half < 2; half++) {
                int rl = rl_base + mt * 16 + half * 8;
                float v0 = acc[mt][nt][half * 2 + 0] + b0;
                float v1 = acc[mt][nt][half * 2 + 1] + b1;
                if (mode & 1) { v0 = fmaxf(v0, 0.f); v1 = fmaxf(v1, 0.f); }
                if (mode & 2) { v0 = tf32r(v0); v1 = tf32r(v1); }
                sC[(rl * 4 + (ncol & 3)) * 32 + (ncol >> 2)] = v0;
                int nc1 = ncol + 1;
                sC[(rl * 4 + (nc1 & 3)) * 32 + (nc1 >> 2)] = v1;
            }
        }
    }
    __syncthreads();
    float4* outp = (float4*)(C + (size_t)m0 * 128);
    const float4* sC4 = (const float4*)sC;
    #pragma unroll
    for (int i = 0; i < 32; i++) outp[tid + i * 128] = sC4[tid + i * 128];
}

// ---------------- We1 GEMM with gathered A: 128 threads, 64x64 warp tiles ----------------
__global__ __launch_bounds__(128, 2)
void mma_gemm_we1(const float* __restrict__ Bt,
                  const float* __restrict__ bias,
                  float* __restrict__ C, int ldc,
                  const int* __restrict__ ei, int E) {
    extern __shared__ char dyn_smem[];
    __shared__ float s_bias[128];
    __shared__ int s_src[128], s_dst[128];
    const uint32_t sbase = smem_u32(dyn_smem);
    const int tid = threadIdx.x;
    const int wid = tid >> 5;
    const int lane = tid & 31;
    const int m0 = blockIdx.y * 128;
    const int n0 = blockIdx.x * 128;
    const int wm = (wid & 1) * 64;
    const int wn = (wid >> 1) * 64;

    s_bias[tid] = bias[n0 + tid];
    s_src[tid] = ei[m0 + tid];
    s_dst[tid] = ei[E + m0 + tid];
    __syncthreads();

    float acc[4][8][4];
    #pragma unroll
    for (int i = 0; i < 4; i++)
        #pragma unroll
        for (int j = 0; j < 8; j++)
            #pragma unroll
            for (int q = 0; q < 4; q++) acc[i][j][q] = 0.f;

#define WE1_LOAD(c, sa_) do {                                                         \
    int seg = (c) >> 2, cbase = ((c) & 3) * 32;                                       \
    uint32_t sb_ = (sa_) + 16384u;                                                    \
    _Pragma("unroll")                                                                 \
    for (int i = 0; i < 8; i++) {                                                     \
        int v = tid + (i << 7);                                                       \
        int row = v >> 3, kq = v & 7;                                                 \
        int col = cbase + kq * 4;                                                     \
        const float* srcp;                                                            \
        if (seg == 0)      srcp = g_xr  + (size_t)s_src[row] * 128 + col;             \
        else if (seg == 1) srcp = g_efr + (size_t)(m0 + row) * 128 + col;             \
        else if (seg == 2) srcp = g_grev + (size_t)(m0 + row) * 128 + col;            \
        else               srcp = g_xr  + (size_t)s_dst[row] * 128 + col;             \
        cp16((sa_) + swz(row * 128 + kq * 16), srcp);                                 \
    }                                                                                 \
    const float* bb = Bt + (size_t)n0 * 512 + (c) * 32;                               \
    _Pragma("unroll")                                                                 \
    for (int i = 0; i < 8; i++) {                                                     \
        int v = tid + (i << 7);                                                       \
        int row = v >> 3, kq = v & 7;                                                 \
        cp16(sb_ + swz(row * 128 + kq * 16), bb + (size_t)row * 512 + kq * 4);        \
    }                                                                                 \
} while (0)

    GEMM_PIPE128(WE1_LOAD, 512, acc)
#undef WE1_LOAD

    const int rbase = m0 + wm + (lane >> 2);
    const int cl = (lane & 3) * 2;
    #pragma unroll
    for (int mt = 0; mt < 4; mt++) {
        #pragma unroll
        for (int nt = 0; nt < 8; nt++) {
            int ncol_l = wn + nt * 8 + cl;
            float b0 = s_bias[ncol_l], b1 = s_bias[ncol_l + 1];
            int ncol = n0 + ncol_l;
            #pragma unroll
            for (int half = 0; half < 2; half++) {
                int row = rbase + mt * 16 + half * 8;
                float v0 = tf32r(fmaxf(acc[mt][nt][half * 2 + 0] + b0, 0.f));
                float v1 = tf32r(fmaxf(acc[mt][nt][half * 2 + 1] + b1, 0.f));
                *(float2*)(C + (size_t)row * ldc + ncol) = make_float2(v0, v1);
            }
        }
    }
}

// ---------------- We2 GEMM (128-thread 64x64) with fused LayerNorm + scatter ----------------
__global__ __launch_bounds__(128, 2)
void mma_gemm_ln128(const float* __restrict__ A, int lda,
                    const float* __restrict__ Bt,
                    const float* __restrict__ bias,
                    float* __restrict__ C,
                    int K,
                    const float* __restrict__ ge, const float* __restrict__ be,
                    const int* __restrict__ ei, int E) {
    extern __shared__ char dyn_smem[];
    __shared__ float s_bias[128];
    __shared__ float s_ge[128];
    __shared__ float s_be[128];
    const uint32_t sbase = smem_u32(dyn_smem);
    const int tid = threadIdx.x;
    const int wid = tid >> 5;
    const int lane = tid & 31;
    const int m0 = blockIdx.y * 128;
    const int n0 = 0;
    const int wm = (wid & 1) * 64;
    const int wn = (wid >> 1) * 64;

    s_bias[tid] = bias[tid];
    s_ge[tid] = ge[tid];
    s_be[tid] = be[tid];

    float acc[4][8][4];
    #pragma unroll
    for (int i = 0; i < 4; i++)
        #pragma unroll
        for (int j = 0; j < 8; j++)
            #pragma unroll
            for (int q = 0; q < 4; q++) acc[i][j][q] = 0.f;

    #define LC_STD128(c, sa) g_load_chunk128(A, lda, Bt, K, m0, n0, c, sa, tid)
    GEMM_PIPE128(LC_STD128, K, acc)
    #undef LC_STD128

    cp_wait0();
    __syncthreads();
    float* sC = (float*)dyn_smem;   // [128][132]
    const int rl_base = wm + (lane >> 2);
    const int cl = (lane & 3) * 2;
    #pragma unroll
    for (int mt = 0; mt < 4; mt++) {
        #pragma unroll
        for (int nt = 0; nt < 8; nt++) {
            int ncol = wn + nt * 8 + cl;
            float b0 = s_bias[ncol], b1 = s_bias[ncol + 1];
            #pragma unroll
            for (int half = 0; half < 2; half++) {
                int rl = rl_base + mt * 16 + half * 8;
                sC[rl * 132 + ncol]     = acc[mt][nt][half * 2 + 0] + b0;
                sC[rl * 132 + ncol + 1] = acc[mt][nt][half * 2 + 1] + b1;
            }
        }
    }
    __syncthreads();
    for (int r = wid; r < 128; r += 4) {
        float4 v = ((float4*)(sC + r * 132))[lane];
        float s = v.x + v.y + v.z + v.w;
        float sq = v.x * v.x + v.y * v.y + v.z * v.z + v.w * v.w;
        #pragma unroll
        for (int off = 16; off; off >>= 1) {
            s  += __shfl_xor_sync(0xffffffffu, s,  off);
            sq += __shfl_xor_sync(0xffffffffu, sq, off);
        }
        float m = s * (1.f / 128.f);
        float var = sq * (1.f / 128.f) - m * m;
        float inv = rsqrtf(var + 1e-5f);
        int e = m0 + r;
        int si = ei[e], di = ei[E + e];
        float* pv = &v.x;
        #pragma unroll
        for (int j = 0; j < 4; j++) {
            int c = lane * 4 + j;
            float val = (pv[j] - m) * inv * s_ge[c] + s_be[c];
            pv[j] = val;
            atomicAdd(&g_subj[si * 128 + c], val);
            atomicAdd(&g_obj[di * 128 + c], val);
        }
        ((float4*)(C + (size_t)e * 128))[lane] = v;
    }
}

// ---------------- fused attention MLP + softmax + scatter-max ----------------
#define AT_SMEM ((4352 + 2176 + 8704 + 8704 + 64 + 32) * 4)
__global__ __launch_bounds__(256, 2)
void attn_fused(const float* __restrict__ pe, const int* __restrict__ ei, int E) {
    extern __shared__ float sm[];
    float* sA1 = sm;
    float* sA2 = sA1 + 4352;
    float* sq  = sA2 + 2176;
    float* st1 = sq + 8704;
    float* sb1 = st1 + 8704;
    float* sb2 = sb1 + 64;
    const int tid = threadIdx.x, wid = tid >> 5, lane = tid & 31;
    for (int i = tid; i < 64 * 64; i += 256) sA1[(i >> 6) * 68 + (i & 63)] = g_wt[WT_A1 + i];
    for (int i = tid; i < 32 * 64; i += 256) sA2[(i >> 6) * 68 + (i & 63)] = g_wt[WT_A2 + i];
    if (tid < 64) sb1[tid] = g_wt[WT_BA1 + tid];
    else if (tid < 96) sb2[tid - 64] = g_wt[WT_BA2 + tid - 64];

    const int R0 = blockIdx.x * 128 + wid * 16;
    float* mysq = sq + wid * 1088;
    float* myt1 = st1 + wid * 1088;
    const float* gpe = pe + (size_t)R0 * 32;
    #pragma unroll
    for (int i = 0; i < 4; i++) {
        int v = lane + i * 32;
        int r = v >> 3, c4 = v & 7;
        float4 pv = ((const float4*)(gpe + r * 32))[c4];
        *(float4*)(mysq + r * 68 + 32 + c4 * 4) = pv;
    }
    #pragma unroll
    for (int r = 0; r < 16; r++) {
        int gr = R0 + r;
        int e = gr >> 2, h = gr & 3;
        int s = ei[e];
        mysq[r * 68 + lane] = g_xq[(size_t)s * 128 + h * 32 + lane];
    }
    __syncthreads();

    const int qr = lane >> 2, qk = lane & 3;
    float acc1[8][4];
    #pragma unroll
    for (int nt = 0; nt < 8; nt++)
        #pragma unroll
        for (int q = 0; q < 4; q++) acc1[nt][q] = 0.f;
    #pragma unroll
    for (int kc = 0; kc < 8; kc++) {
        uint32_t a[4];
        a[0] = __float_as_uint(mysq[qr * 68 + kc * 8 + qk]);
        a[1] = __float_as_uint(mysq[(qr + 8) * 68 + kc * 8 + qk]);
        a[2] = __float_as_uint(mysq[qr * 68 + kc * 8 + qk + 4]);
        a[3] = __float_as_uint(mysq[(qr + 8) * 68 + kc * 8 + qk + 4]);
        #pragma unroll
        for (int nt = 0; nt < 8; nt++) {
            uint32_t b0 = __float_as_uint(sA1[(nt * 8 + qr) * 68 + kc * 8 + qk]);
            uint32_t b1 = __float_as_uint(sA1[(nt * 8 + qr) * 68 + kc * 8 + qk + 4]);
            mma8(acc1[nt], a, b0, b1);
        }
    }
    #pragma unroll
    for (int nt = 0; nt < 8; nt++) {
        int c0 = nt * 8 + 2 * qk;
        float b0v = sb1[c0], b1v = sb1[c0 + 1];
        myt1[qr * 68 + c0]           = tf32r(fmaxf(acc1[nt][0] + b0v, 0.f));
        myt1[qr * 68 + c0 + 1]       = tf32r(fmaxf(acc1[nt][1] + b1v, 0.f));
        myt1[(qr + 8) * 68 + c0]     = tf32r(fmaxf(acc1[nt][2] + b0v, 0.f));
        myt1[(qr + 8) * 68 + c0 + 1] = tf32r(fmaxf(acc1[nt][3] + b1v, 0.f));
    }
    __syncwarp();
    float acc2[4][4];
    #pragma unroll
    for (int nt = 0; nt < 4; nt++)
        #pragma unroll
        for (int q = 0; q < 4; q++) acc2[nt][q] = 0.f;
    #pragma unroll
    for (int kc = 0; kc < 8; kc++) {
        uint32_t a[4];
        a[0] = __float_as_uint(myt1[qr * 68 + kc * 8 + qk]);
        a[1] = __float_as_uint(myt1[(qr + 8) * 68 + kc * 8 + qk]);
        a[2] = __float_as_uint(myt1[qr * 68 + kc * 8 + qk + 4]);
        a[3] = __float_as_uint(myt1[(qr + 8) * 68 + kc * 8 + qk + 4]);
        #pragma unroll
        for (int nt = 0; nt < 4; nt++) {
            uint32_t b0 = __float_as_uint(sA2[(nt * 8 + qr) * 68 + kc * 8 + qk]);
            uint32_t b1 = __float_as_uint(sA2[(nt * 8 + qr) * 68 + kc * 8 + qk + 4]);
            mma8(acc2[nt], a, b0, b1);
        }
    }
    float vlo[8], vhi[8];
    #pragma unroll
    for (int nt = 0; nt < 4; nt++) {
        int c0 = nt * 8 + 2 * qk;
        vlo[nt * 2]     = acc2[nt][0] + sb2[c0];
        vlo[nt * 2 + 1] = acc2[nt][1] + sb2[c0 + 1];
        vhi[nt * 2]     = acc2[nt][2] + sb2[c0];
        vhi[nt * 2 + 1] = acc2[nt][3] + sb2[c0 + 1];
    }
    float mlo = vlo[0], mhi = vhi[0];
    #pragma unroll
    for (int i = 1; i < 8; i++) { mlo = fmaxf(mlo, vlo[i]); mhi = fmaxf(mhi, vhi[i]); }
    mlo = fmaxf(mlo, __shfl_xor_sync(0xffffffffu, mlo, 1));
    mlo = fmaxf(mlo, __shfl_xor_sync(0xffffffffu, mlo, 2));
    mhi = fmaxf(mhi, __shfl_xor_sync(0xffffffffu, mhi, 1));
    mhi = fmaxf(mhi, __shfl_xor_sync(0xffffffffu, mhi, 2));
    float slo = 0.f, shi = 0.f;
    #pragma unroll
    for (int i = 0; i < 8; i++) {
        vlo[i] = expf(vlo[i] - mlo); slo += vlo[i];
        vhi[i] = expf(vhi[i] - mhi); shi += vhi[i];
    }
    slo += __shfl_xor_sync(0xffffffffu, slo, 1);
    slo += __shfl_xor_sync(0xffffffffu, slo, 2);
    shi += __shfl_xor_sync(0xffffffffu, shi, 1);
    shi += __shfl_xor_sync(0xffffffffu, shi, 2);
    float rlo = 1.f / slo, rhi = 1.f / shi;
    int Rlo = R0 + qr, Rhi = R0 + qr + 8;
    int elo = Rlo >> 2, hlo = Rlo & 3;
    int ehi = Rhi >> 2, hhi = Rhi & 3;
    int silo = ei[elo], sihi = ei[ehi];
    int dlo = ei[E + elo], dhi = ei[E + ehi];
    const float* vblo = g_xv + (size_t)dlo * 128 + hlo * 32;
    const float* vbhi = g_xv + (size_t)dhi * 128 + hhi * 32;
    unsigned* seglo = g_seg + silo * 128 + hlo;
    unsigned* seghi = g_seg + sihi * 128 + hhi;
    #pragma unroll
    for (int nt = 0; nt < 4; nt++) {
        #pragma unroll
        for (int j = 0; j < 2; j++) {
            int o = nt * 8 + 2 * qk + j;
            float xlo = vlo[nt * 2 + j] * rlo * vblo[o];
            atomicMax(&seglo[o * 4], f2o(xlo));
            float xhi = vhi[nt * 2 + j] * rhi * vbhi[o];
            atomicMax(&seghi[o * 4], f2o(xhi));
        }
    }
}

// ---------------- generic tiled fp32 SGEMM (node GEMMs + fallback) ----------------
__global__ __launch_bounds__(128)
void sgemm(const float* __restrict__ A, int lda,
           const float* __restrict__ W,
           const float* __restrict__ bias,
           float* __restrict__ C, int ldc,
           int M, int K, int N, int act) {
    __shared__ __align__(16) float As[16][64];
    __shared__ __align__(16) float Bs[16][64];
    int t = threadIdx.x;
    int m0 = blockIdx.y * 64;
    int n0 = blockIdx.x * 64;
    int tx = t & 15;
    int ty = t >> 4;
    float acc[8][4];
    #pragma unroll
    for (int i = 0; i < 8; i++)
        #pragma unroll
        for (int j = 0; j < 4; j++) acc[i][j] = 0.f;

    for (int k0 = 0; k0 < K; k0 += 16) {
        #pragma unroll
        for (int i = 0; i < 2; i++) {
            int v = t * 2 + i;
            int row = v >> 2;
            int kq = v & 3;
            float4 av = make_float4(0.f, 0.f, 0.f, 0.f);
            int gr = m0 + row;
            if (gr < M) av = *(const float4*)(A + (size_t)gr * lda + k0 + kq * 4);
            As[kq * 4 + 0][row] = av.x;
            As[kq * 4 + 1][row] = av.y;
            As[kq * 4 + 2][row] = av.z;
            As[kq * 4 + 3][row] = av.w;
        }
        #pragma unroll
        for (int i = 0; i < 2; i++) {
            int v = t * 2 + i;
            int kr = v >> 4;
            int nq = v & 15;
            *(float4*)&Bs[kr][nq * 4] = *(const float4*)(W + (size_t)(k0 + kr) * N + n0 + nq * 4);
        }
        __syncthreads();
        #pragma unroll
        for (int kk = 0; kk < 16; kk++) {
            float a[8], b[4];
            *(float4*)&a[0] = *(float4*)&As[kk][ty * 8];
            *(float4*)&a[4] = *(float4*)&As[kk][ty * 8 + 4];
            *(float4*)&b[0] = *(float4*)&Bs[kk][tx * 4];
            #pragma unroll
            for (int i = 0; i < 8; i++)
                #pragma unroll
                for (int j = 0; j < 4; j++) acc[i][j] += a[i] * b[j];
        }
        __syncthreads();
    }
    float bv[4];
    #pragma unroll
    for (int j = 0; j < 4; j++) bv[j] = bias[n0 + tx * 4 + j];
    #pragma unroll
    for (int i = 0; i < 8; i++) {
        int gr = m0 + ty * 8 + i;
        if (gr >= M) continue;
        float4 o;
        float* po = &o.x;
        #pragma unroll
        for (int j = 0; j < 4; j++) {
            float v = acc[i][j] + bv[j];
            if (act) v = fmaxf(v, 0.f);
            po[j] = v;
        }
        *(float4*)(C + (size_t)gr * ldc + n0 + tx * 4) = o;
    }
}

// ================= legacy fallback kernels (E % 128 != 0 only) =================
__global__ void gather_gate_legacy(const float* __restrict__ x, const float* __restrict__ ef,
                                   const int* __restrict__ ei,
                                   const float* __restrict__ Wg1, const float* __restrict__ bg1,
                                   const float* __restrict__ Wg2, const float* __restrict__ bg2,
                                   int E, int Nn) {
    __shared__ __align__(16) float sW[128 * 64];
    __shared__ float sW2[64];
    __shared__ float sb1[64];
    __shared__ float sbg2;
    __shared__ __align__(16) float sefs[8][128];
    int t = threadIdx.x;
    for (int i = t; i < 128 * 64; i += 256) sW[i] = Wg1[i];
    if (t < 64) { sW2[t] = Wg2[t]; sb1[t] = bg1[t]; }
    if (t == 0) sbg2 = bg2[0];
    __syncthreads();
    int w = t >> 5, lane = t & 31;
    int e = blockIdx.x * 8 + w;
    if (e >= E) return;
    int s = ei[e], d = ei[E + e];
    float4 efv = ((const float4*)(ef + (size_t)e * 128))[lane];
    *(float4*)&sefs[w][lane * 4] = efv;
    __syncwarp();
    float g0 = sb1[lane], g1 = sb1[lane + 32];
    #pragma unroll 8
    for (int k = 0; k < 128; k++) {
        float ev = sefs[w][k];
        g0 += ev * sW[k * 64 + lane];
        g1 += ev * sW[k * 64 + lane + 32];
    }
    g0 = fmaxf(g0, 0.f); g1 = fmaxf(g1, 0.f);
    float p = g0 * sW2[lane] + g1 * sW2[lane + 32];
    #pragma unroll
    for (int off = 16; off; off >>= 1) p += __shfl_xor_sync(0xffffffffu, p, off);
    float gate = 1.f / (1.f + expf(-(p + sbg2)));
    int rid = -1;
    if (lane == 0) {
        unsigned rkey = (unsigned)d * (unsigned)Nn + (unsigned)s;
        rid = hash_find(rkey);
        atomicAdd(&g_cnt_s[s], 1);
        atomicAdd(&g_cnt_d[d], 1);
    }
    rid = __shfl_sync(0xffffffffu, rid, 0);
    float4 rv = make_float4(0.f, 0.f, 0.f, 0.f);
    if (rid >= 0) {
        rv = ((const float4*)(ef + (size_t)rid * 128))[lane];
        rv.x *= gate; rv.y *= gate; rv.z *= gate; rv.w *= gate;
    }
    float4 xi = ((const float4*)(x + (size_t)s * 128))[lane];
    float4 xj = ((const float4*)(x + (size_t)d * 128))[lane];
    float* dst = g_efc + (size_t)e * 512;
    ((float4*)dst)[lane]          = xi;
    ((float4*)(dst + 128))[lane]  = efv;
    ((float4*)(dst + 256))[lane]  = rv;
    ((float4*)(dst + 384))[lane]  = xj;
}

__global__ void edge_ln_scatter(float* __restrict__ out_edge,
                                const float* __restrict__ ge, const float* __restrict__ be,
                                const int* __restrict__ ei, int E) {
    int t = threadIdx.x;
    int w = t >> 5, lane = t & 31;
    int e = blockIdx.x * 8 + w;
    if (e >= E) return;
    float* row = out_edge + (size_t)e * 128;
    float4 v = ((float4*)row)[lane];
    float s = v.x + v.y + v.z + v.w;
    float sq = v.x * v.x + v.y * v.y + v.z * v.z + v.w * v.w;
    #pragma unroll
    for (int off = 16; off; off >>= 1) {
        s  += __shfl_xor_sync(0xffffffffu, s,  off);
        sq += __shfl_xor_sync(0xffffffffu, sq, off);
    }
    float m = s * (1.f / 128.f);
    float var = sq * (1.f / 128.f) - m * m;
    float inv = rsqrtf(var + 1e-5f);
    int si = ei[e], di = ei[E + e];
    float* pv = &v.x;
    #pragma unroll
    for (int j = 0; j < 4; j++) {
        int c = lane * 4 + j;
        float val = (pv[j] - m) * inv * ge[c] + be[c];
        pv[j] = val;
        atomicAdd(&g_subj[si * 128 + c], val);
        atomicAdd(&g_obj[di * 128 + c], val);
    }
    ((float4*)row)[lane] = v;
}

__global__ __launch_bounds__(128)
void attention_kernel(const float* __restrict__ qb, const float* __restrict__ peb,
                      const float* __restrict__ vb,
                      const float* __restrict__ A1, const float* __restrict__ a1,
                      const float* __restrict__ A2, const float* __restrict__ a2,
                      const int* __restrict__ ei, int E) {
    __shared__ float sA1[64 * 64];
    __shared__ float sA2[32 * 64];
    __shared__ float sa1[64], sa2[32];
    int t = threadIdx.x;
    for (int i = t; i < 4096; i += 128) sA1[i] = A1[i];
    for (int i = t; i < 2048; i += 128) sA2[i] = A2[i];
    if (t < 64) sa1[t] = a1[t];
    if (t < 32) sa2[t] = a2[t];
    __syncthreads();
    int p = blockIdx.x * 128 + t;
    if (p >= E * 4) return;
    int e = p >> 2, h = p & 3;
    const float* qr = qb + (size_t)e * 128 + h;
    const float* pr = peb + (size_t)e * 128 + h;
    float hv[64];
    #pragma unroll
    for (int c = 0; c < 32; c++) { hv[c] = qr[c * 4]; hv[32 + c] = pr[c * 4]; }
    float t1[64];
    #pragma unroll
    for (int o = 0; o < 64; o++) {
        float acc = sa1[o];
        #pragma unroll
        for (int c = 0; c < 64; c++) acc += sA1[o * 64 + c] * hv[c];
        t1[o] = fmaxf(acc, 0.f);
    }
    float t2[32];
    float mx = -1e30f;
    #pragma unroll
    for (int o = 0; o < 32; o++) {
        float acc = sa2[o];
        #pragma unroll
        for (int c = 0; c < 64; c++) acc += sA2[o * 64 + c] * t1[c];
        t2[o] = acc;
        mx = fmaxf(mx, acc);
    }
    float ssum = 0.f;
    #pragma unroll
    for (int o = 0; o < 32; o++) { t2[o] = expf(t2[o] - mx); ssum += t2[o]; }
    float rs = 1.f / ssum;
    int s = ei[e];
    const float* vr = vb + (size_t)e * 128 + h;
    unsigned* segb = g_seg + s * 128 + h;
    #pragma unroll
    for (int o = 0; o < 32; o++) {
        float xxv = t2[o] * rs * vr[o * 4];
        atomicMax(&segb[o * 4], f2o(xxv));
    }
}

// ---------------- node pipeline ----------------
__global__ void node_pre1(int Nn) {
    int i = blockIdx.x * 256 + threadIdx.x;
    if (i >= Nn * 128) return;
    int n = i >> 7, c = i & 127;
    float cs = fmaxf((float)g_cnt_s[n], 1.f);
    float cd = fmaxf((float)g_cnt_d[n], 1.f);
    g_twin_in[n * 256 + c]       = g_subj[i] / cs;
    g_twin_in[n * 256 + 128 + c] = g_obj[i] / cd;
}

__global__ void node_pre2(const float* __restrict__ x, int Nn) {
    int i = blockIdx.x * 256 + threadIdx.x;
    if (i >= Nn * 128) return;
    int n = i >> 7, c = i & 127;
    float tw = g_twin[i];
    float sg = 1.f / (1.f + expf(-tw));
    float xx = 0.f;
    if (g_cnt_s[n] > 0) xx = fmaxf(o2f(g_seg[i]), 0.f);
    g_pin[n * 256 + c]       = x[i];
    g_pin[n * 256 + 128 + c] = xx * sg;
}

__global__ void node_ln(float* __restrict__ out_node,
                        const float* __restrict__ gn, const float* __restrict__ bn,
                        int Nn) {
    int t = threadIdx.x;
    int w = t >> 5, lane = t & 31;
    int n = blockIdx.x * 8 + w;
    if (n >= Nn) return;
    float* row = out_node + (size_t)n * 128;
    float4 v = ((float4*)row)[lane];
    float s = v.x + v.y + v.z + v.w;
    float sq = v.x * v.x + v.y * v.y + v.z * v.z + v.w * v.w;
    #pragma unroll
    for (int off = 16; off; off >>= 1) {
        s  += __shfl_xor_sync(0xffffffffu, s,  off);
        sq += __shfl_xor_sync(0xffffffffu, sq, off);
    }
    float m = s * (1.f / 128.f);
    float var = sq * (1.f / 128.f) - m * m;
    float inv = rsqrtf(var + 1e-5f);
    float* pv = &v.x;
    #pragma unroll
    for (int j = 0; j < 4; j++) {
        int c = lane * 4 + j;
        pv[j] = (pv[j] - m) * inv * gn[c] + bn[c];
    }
    ((float4*)row)[lane] = v;
}

// ---------------- launch ----------------
extern "C" void kernel_launch(void* const* d_in, const int* in_sizes, int n_in,
                              void* d_out, int out_size) {
    const float* x    = (const float*)d_in[0];
    const float* ef   = (const float*)d_in[1];
    const int*   ei   = (const int*)  d_in[2];
    const float* Wg1  = (const float*)d_in[3];
    const float* bg1  = (const float*)d_in[4];
    const float* Wg2  = (const float*)d_in[5];
    const float* bg2  = (const float*)d_in[6];
    const float* We1  = (const float*)d_in[7];
    const float* be1  = (const float*)d_in[8];
    const float* We2  = (const float*)d_in[9];
    const float* be2  = (const float*)d_in[10];
    const float* ge   = (const float*)d_in[11];
    const float* bee  = (const float*)d_in[12];
    const float* Wq   = (const float*)d_in[13];
    const float* bq   = (const float*)d_in[14];
    const float* Wpe  = (const float*)d_in[15];
    const float* bpe  = (const float*)d_in[16];
    const float* Wv   = (const float*)d_in[17];
    const float* bv   = (const float*)d_in[18];
    const float* A1   = (const float*)d_in[19];
    const float* a1   = (const float*)d_in[20];
    const float* A2   = (const float*)d_in[21];
    const float* a2   = (const float*)d_in[22];
    const float* Wt   = (const float*)d_in[23];
    const float* bt   = (const float*)d_in[24];
    const float* Wp1  = (const float*)d_in[25];
    const float* bp1  = (const float*)d_in[26];
    const float* Wp2  = (const float*)d_in[27];
    const float* bp2  = (const float*)d_in[28];
    const float* gn   = (const float*)d_in[29];
    const float* bn   = (const float*)d_in[30];

    int Nn = in_sizes[0] / 128;
    int E  = in_sizes[1] / 128;

    float* out_node = (float*)d_out;
    float* out_edge = out_node + (size_t)Nn * 128;

    float *p_efc, *p_h1, *p_qpe, *p_v, *p_efr, *p_xr, *p_xq, *p_xv;
    float *p_twin_in, *p_twin, *p_pin, *p_hn, *p_wt;
    cudaGetSymbolAddress((void**)&p_efc, g_efc);
    cudaGetSymbolAddress((void**)&p_h1,  g_h1);
    cudaGetSymbolAddress((void**)&p_qpe, g_qpe);
    cudaGetSymbolAddress((void**)&p_v,   g_v);
    cudaGetSymbolAddress((void**)&p_efr, g_efr);
    cudaGetSymbolAddress((void**)&p_xr,  g_xr);
    cudaGetSymbolAddress((void**)&p_xq,  g_xq);
    cudaGetSymbolAddress((void**)&p_xv,  g_xv);
    cudaGetSymbolAddress((void**)&p_twin_in, g_twin_in);
    cudaGetSymbolAddress((void**)&p_twin, g_twin);
    cudaGetSymbolAddress((void**)&p_pin, g_pin);
    cudaGetSymbolAddress((void**)&p_hn,  g_hn);
    cudaGetSymbolAddress((void**)&p_wt,  g_wt);

    cudaFuncSetAttribute(mma_gemm, cudaFuncAttributeMaxDynamicSharedMemorySize, G_SMEM);
    cudaFuncSetAttribute(mma_gemm128, cudaFuncAttributeMaxDynamicSharedMemorySize, G_SMEM);
    cudaFuncSetAttribute(mma_gemm_we1, cudaFuncAttributeMaxDynamicSharedMemorySize, G_SMEM);
    cudaFuncSetAttribute(mma_gemm_ln128, cudaFuncAttributeMaxDynamicSharedMemorySize, G_SMEM);
    cudaFuncSetAttribute(attn_fused, cudaFuncAttributeMaxDynamicSharedMemorySize, AT_SMEM);

    int gNn = (Nn + 63) / 64;
    int ntiles = (Nn + 127) / 128;
    int npad = ntiles * 128;
    bool use_tc = (E % 128) == 0 && Nn <= MAX_N;
    int rx_blocks = (npad * 128 + 255) / 256;
    int prep_blocks = 512 + 291 + rx_blocks;

    if (use_tc) {
        int mt = E / 128;
        int gg_blocks = (E + 31) / 32;
        if (gg_blocks > 1184) gg_blocks = 1184;
        // order: prep(0), hash(1), gather(2), we1(3 = ncu -s 5 profiled slot)
        prep_all<<<prep_blocks, 256>>>(We1, We2, Wq, Wpe, Wv, A1, a1, A2, a2, x, Nn, npad);
        hash_build<<<(E + 255) / 256, 256>>>(ei, E, Nn);
        gather_gate<<<gg_blocks, 256>>>(ef, ei, Wg1, bg1, Wg2, bg2, E, Nn);
        mma_gemm_we1<<<dim3(3, mt), 128, G_SMEM>>>(p_wt + WT_WE1, be1, p_h1, 384, ei, E);
        mma_gemm<<<dim3(1, ntiles), 256, G_SMEM>>>(p_xr, 128, p_wt + WT_WQ, bq, p_xq, 0, 128, 10, 128, 0, 0);
        mma_gemm<<<dim3(1, ntiles), 256, G_SMEM>>>(p_xr, 128, p_wt + WT_WV, bv, p_xv, 0, 128, 8, 128, 0, 0);
        mma_gemm_ln128<<<dim3(1, mt), 128, G_SMEM>>>(p_h1, 384, p_wt + WT_WE2, be2, out_edge, 384, ge, bee, ei, E);
        mma_gemm128<<<dim3(1, mt), 128, G_SMEM>>>(p_efr, 128, p_wt + WT_WPE, bpe, p_qpe, 128, 2);
        attn_fused<<<E / 32, 256, AT_SMEM>>>(p_qpe, ei, E);
    } else {
        prep_all<<<prep_blocks, 256>>>(We1, We2, Wq, Wpe, Wv, A1, a1, A2, a2, x, Nn, npad);
        hash_build<<<(E + 255) / 256, 256>>>(ei, E, Nn);
        int gE = (E + 63) / 64;
        float* p_q  = p_qpe;
        float* p_pe = p_qpe + (size_t)E * 128;
        gather_gate_legacy<<<(E + 7) / 8, 256>>>(x, ef, ei, Wg1, bg1, Wg2, bg2, E, Nn);
        sgemm<<<dim3(6, gE), 128>>>(p_efc, 512, We1, be1, p_h1, 384, E, 512, 384, 1);
        sgemm<<<dim3(2, gE), 128>>>(p_h1, 384, We2, be2, out_edge, 128, E, 384, 128, 0);
        edge_ln_scatter<<<(E + 7) / 8, 256>>>(out_edge, ge, bee, ei, E);
        sgemm<<<dim3(2, gE), 128>>>(p_efc +   0, 512, Wq,  bq,  p_q,  128, E, 128, 128, 0);
        sgemm<<<dim3(2, gE), 128>>>(p_efc + 128, 512, Wpe, bpe, p_pe, 128, E, 128, 128, 0);
        sgemm<<<dim3(2, gE), 128>>>(p_efc + 384, 512, Wv,  bv,  p_v,  128, E, 128, 128, 0);
        attention_kernel<<<(E * 4 + 127) / 128, 128>>>(p_q, p_pe, p_v, A1, a1, A2, a2, ei, E);
    }

    node_pre1<<<(Nn * 128 + 255) / 256, 256>>>(Nn);
    sgemm<<<dim3(2, gNn), 128>>>(p_twin_in, 256, Wt, bt, p_twin, 128, Nn, 256, 128, 0);
    node_pre2<<<(Nn * 128 + 255) / 256, 256>>>(x, Nn);
    sgemm<<<dim3(4, gNn), 128>>>(p_pin, 256, Wp1, bp1, p_hn, 256, Nn, 256, 256, 1);
    sgemm<<<dim3(2, gNn), 128>>>(p_hn, 256, Wp2, bp2, out_node, 128, Nn, 256, 128, 0);
    node_ln<<<(Nn + 7) / 8, 256>>>(out_node, gn, bn, Nn);
}